// round 13
// baseline (speedup 1.0000x reference)
#include <cuda_runtime.h>
#include <cuda_fp16.h>
#include <math.h>
#include <stdint.h>

// Problem constants
#define BB   128
#define NN   196
#define CC   768
#define HH   8
#define HD   96
#define MROWS (BB*NN)   // 25088
#define BHD   (BB*HH)   // 1024

// -------- device scratch (no runtime allocation allowed) --------
__device__ float g_Q[(size_t)MROWS*CC];
__device__ float g_K[(size_t)MROWS*CC];
__device__ float g_V[(size_t)MROWS*CC];
__device__ float g_invsc[CC];
__device__ __half g_xh[(size_t)MROWS*CC];
__device__ __half g_xl[(size_t)MROWS*CC];
__device__ __half g_ah[(size_t)MROWS*CC];
__device__ __half g_wh[(size_t)4*CC*CC];
__device__ __half g_wl[(size_t)4*CC*CC];

// ======================= PTX helpers =======================
__device__ __forceinline__ uint32_t s2u(const void* p) {
    uint32_t a;
    asm("{ .reg .u64 t; cvta.to.shared.u64 t, %1; cvt.u32.u64 %0, t; }" : "=r"(a) : "l"(p));
    return a;
}

#define CP16(d, s) asm volatile("cp.async.cg.shared.global [%0], [%1], 16;" :: "r"(d), "l"(s))
#define CP_COMMIT() asm volatile("cp.async.commit_group;" ::: "memory")
#define CP_WAIT(n)  asm volatile("cp.async.wait_group %0;" :: "n"(n) : "memory")

#define LDSM4(r0, r1, r2, r3, a) \
    asm volatile("ldmatrix.sync.aligned.m8n8.x4.shared.b16 {%0,%1,%2,%3}, [%4];" \
        : "=r"(r0), "=r"(r1), "=r"(r2), "=r"(r3) : "r"(a))

#define MMA(dp, a, b0, b1) \
    asm volatile("mma.sync.aligned.m16n8k16.row.col.f32.f16.f16.f32 " \
        "{%0,%1,%2,%3},{%4,%5,%6,%7},{%8,%9},{%0,%1,%2,%3};" \
        : "+f"((dp)[0]), "+f"((dp)[1]), "+f"((dp)[2]), "+f"((dp)[3]) \
        : "r"((a)[0]), "r"((a)[1]), "r"((a)[2]), "r"((a)[3]), "r"(b0), "r"(b1))

// smem chunk swizzle: element row r (64B rows), 16B chunk c (0..3) -> byte offset
__device__ __forceinline__ uint32_t swoff(int r, int c) {
    return (uint32_t)(r * 64 + ((c ^ ((r >> 1) & 3)) << 4));
}

#define GITERS 24

// ======================= 3-term fp16 GEMM (measured 211us) =====
// D = Ah*Bh + Ah*Bl + Al*Bh + bias (+pos).
// CTA 128x256, warp 64x64, BK=32, 4-stage cp.async, 192KB smem, occ 1.
#define G3STGB 49152
#define G3AH   0
#define G3AL   8192
#define G3BH   16384
#define G3BL   32768
#define SMEM_G3 (4*G3STGB)  // 196608

__global__ __launch_bounds__(256, 1) void gemm3_f16(
    const __half* __restrict__ Ah, const __half* __restrict__ Al,
    const __half* __restrict__ Bh, const __half* __restrict__ Bl,
    const float* __restrict__ bias, const float* __restrict__ pos,
    float* __restrict__ C, int addPos)
{
    extern __shared__ char smem[];
    const uint32_t sb = s2u(smem);
    const int tid  = threadIdx.x;
    const int lane = tid & 31;
    const int wid  = tid >> 5;
    const int wm   = (wid & 1) * 64;
    const int wn   = (wid >> 1) * 64;
    const int bm   = blockIdx.y * 128;
    const int bn   = blockIdx.x * 256;

#define LOAD_STAGE3(s, kit) do {                                              \
    int k0 = (kit) * 32;                                                      \
    uint32_t st = sb + (uint32_t)(s) * G3STGB;                                \
    _Pragma("unroll")                                                         \
    for (int i = 0; i < 2; i++) {                                             \
        int u = i * 256 + tid; int r = u >> 2, c = u & 3;                     \
        uint32_t so = swoff(r, c);                                            \
        size_t go = (size_t)(bm + r) * CC + k0 + c * 8;                       \
        CP16(st + G3AH + so, Ah + go);                                        \
        CP16(st + G3AL + so, Al + go);                                        \
    }                                                                         \
    _Pragma("unroll")                                                         \
    for (int i = 0; i < 4; i++) {                                             \
        int u = i * 256 + tid; int r = u >> 2, c = u & 3;                     \
        uint32_t so = swoff(r, c);                                            \
        size_t go = (size_t)(bn + r) * CC + k0 + c * 8;                       \
        CP16(st + G3BH + so, Bh + go);                                        \
        CP16(st + G3BL + so, Bl + go);                                        \
    }                                                                         \
    CP_COMMIT();                                                              \
} while (0)

    float acc[4][8][4];
#pragma unroll
    for (int a = 0; a < 4; a++)
#pragma unroll
        for (int b = 0; b < 8; b++)
#pragma unroll
            for (int c = 0; c < 4; c++) acc[a][b][c] = 0.f;

    LOAD_STAGE3(0, 0);
    LOAD_STAGE3(1, 1);
    LOAD_STAGE3(2, 2);

    const int arow = lane & 15;
    const int achk = lane >> 4;
    const int brow = (lane & 7) + ((lane >> 4) & 1) * 8;
    const int bchk = (lane >> 3) & 1;

    for (int it = 0; it < GITERS; ++it) {
        int rem = GITERS - 1 - it;
        if (rem >= 2) { CP_WAIT(2); }
        else if (rem == 1) { CP_WAIT(1); }
        else { CP_WAIT(0); }
        __syncthreads();

        int ld = it + 3;
        if (ld < GITERS) LOAD_STAGE3(ld & 3, ld);

        uint32_t st = sb + (uint32_t)(it & 3) * G3STGB;
#pragma unroll
        for (int kk = 0; kk < 2; kk++) {
            uint32_t ahf[4][4], alf[4][4];
#pragma unroll
            for (int mt = 0; mt < 4; mt++) {
                int row = wm + mt * 16 + arow;
                uint32_t off = swoff(row, kk * 2 + achk);
                LDSM4(ahf[mt][0], ahf[mt][1], ahf[mt][2], ahf[mt][3], st + G3AH + off);
                LDSM4(alf[mt][0], alf[mt][1], alf[mt][2], alf[mt][3], st + G3AL + off);
            }
#pragma unroll
            for (int bq = 0; bq < 4; bq++) {
                int row = wn + bq * 16 + brow;
                uint32_t off = swoff(row, kk * 2 + bchk);
                uint32_t bh0, bh1, bh2, bh3, bl0, bl1, bl2, bl3;
                LDSM4(bh0, bh1, bh2, bh3, st + G3BH + off);
                LDSM4(bl0, bl1, bl2, bl3, st + G3BL + off);
#pragma unroll
                for (int mt = 0; mt < 4; mt++) {
                    MMA(acc[mt][bq * 2],     ahf[mt], bh0, bh1);
                    MMA(acc[mt][bq * 2],     ahf[mt], bl0, bl1);
                    MMA(acc[mt][bq * 2],     alf[mt], bh0, bh1);
                    MMA(acc[mt][bq * 2 + 1], ahf[mt], bh2, bh3);
                    MMA(acc[mt][bq * 2 + 1], ahf[mt], bl2, bl3);
                    MMA(acc[mt][bq * 2 + 1], alf[mt], bh2, bh3);
                }
            }
        }
    }

#pragma unroll
    for (int mt = 0; mt < 4; mt++) {
#pragma unroll
        for (int i = 0; i < 2; i++) {
            int grow = bm + wm + mt * 16 + (lane >> 2) + i * 8;
            int prow = grow % NN;
            float* crow = C + (size_t)grow * CC;
            const float* pr = pos + (size_t)prow * CC;
#pragma unroll
            for (int nq = 0; nq < 8; nq++) {
                int col = bn + wn + nq * 8 + (lane & 3) * 2;
                float2 o;
                o.x = acc[mt][nq][i * 2]     + bias[col];
                o.y = acc[mt][nq][i * 2 + 1] + bias[col + 1];
                if (addPos) { o.x += pr[col]; o.y += pr[col + 1]; }
                *(float2*)(crow + col) = o;
            }
        }
    }
#undef LOAD_STAGE3
}

// ======================= 2-term fp16 GEMM (measured 146us) =================
// D = Ah*(Bh+Bl) + bias (+pos).  CTA 128x128, warp 64x32, BK=32, 3 stages, occ 2.
#define STGB   32768
#define OAH    0
#define OBH    16384
#define OBL    24576

__global__ __launch_bounds__(256, 2) void gemm2_f16(
    const __half* __restrict__ Ah,
    const __half* __restrict__ Bh, const __half* __restrict__ Bl,
    const float* __restrict__ bias, const float* __restrict__ pos,
    float* __restrict__ C, int addPos)
{
    extern __shared__ char smem[];
    const uint32_t sb = s2u(smem);
    const int tid  = threadIdx.x;
    const int lane = tid & 31;
    const int wid  = tid >> 5;
    const int wm   = (wid & 1) * 64;
    const int wn   = (wid >> 1) * 32;
    const int bm   = blockIdx.y * 128;
    const int bn   = blockIdx.x * 128;

#define LOAD_STAGE2(s, kit) do {                                              \
    int k0 = (kit) * 32;                                                      \
    uint32_t st = sb + (uint32_t)(s) * STGB;                                  \
    _Pragma("unroll")                                                         \
    for (int i = 0; i < 2; i++) {                                             \
        int u = i * 256 + tid; int r = u >> 2, c = u & 3;                     \
        uint32_t so = swoff(r, c);                                            \
        size_t ga = (size_t)(bm + r) * CC + k0 + c * 8;                       \
        size_t gb = (size_t)(bn + r) * CC + k0 + c * 8;                       \
        CP16(st + OAH + so, Ah + ga);                                         \
        CP16(st + OBH + so, Bh + gb);                                         \
        CP16(st + OBL + so, Bl + gb);                                         \
    }                                                                         \
    CP_COMMIT();                                                              \
} while (0)

    float acc[4][4][4];
#pragma unroll
    for (int a = 0; a < 4; a++)
#pragma unroll
        for (int b = 0; b < 4; b++)
#pragma unroll
            for (int c = 0; c < 4; c++) acc[a][b][c] = 0.f;

    LOAD_STAGE2(0, 0);
    LOAD_STAGE2(1, 1);

    const int arow = lane & 15;
    const int achk = lane >> 4;
    const int brow = (lane & 7) + ((lane >> 4) & 1) * 8;
    const int bchk = (lane >> 3) & 1;

    int slot = 0;
    for (int it = 0; it < GITERS; ++it) {
        if (it == GITERS - 1) { CP_WAIT(0); } else { CP_WAIT(1); }
        __syncthreads();

        int ld = it + 2;
        if (ld < GITERS) {
            int ls = slot + 2; if (ls >= 3) ls -= 3;
            LOAD_STAGE2(ls, ld);
        }

        uint32_t st = sb + (uint32_t)slot * STGB;
#pragma unroll
        for (int kk = 0; kk < 2; kk++) {
            uint32_t ahf[4][4];
#pragma unroll
            for (int mt = 0; mt < 4; mt++) {
                int row = wm + mt * 16 + arow;
                uint32_t off = swoff(row, kk * 2 + achk);
                LDSM4(ahf[mt][0], ahf[mt][1], ahf[mt][2], ahf[mt][3], st + OAH + off);
            }
#pragma unroll
            for (int g = 0; g < 2; g++) {
                int row = wn + g * 16 + brow;
                uint32_t off = swoff(row, kk * 2 + bchk);
                uint32_t bh0, bh1, bh2, bh3, bl0, bl1, bl2, bl3;
                LDSM4(bh0, bh1, bh2, bh3, st + OBH + off);
                LDSM4(bl0, bl1, bl2, bl3, st + OBL + off);
#pragma unroll
                for (int mt = 0; mt < 4; mt++) {
                    MMA(acc[mt][g * 2],     ahf[mt], bh0, bh1);
                    MMA(acc[mt][g * 2],     ahf[mt], bl0, bl1);
                    MMA(acc[mt][g * 2 + 1], ahf[mt], bh2, bh3);
                    MMA(acc[mt][g * 2 + 1], ahf[mt], bl2, bl3);
                }
            }
        }
        if (++slot >= 3) slot = 0;
    }

#pragma unroll
    for (int mt = 0; mt < 4; mt++) {
#pragma unroll
        for (int i = 0; i < 2; i++) {
            int grow = bm + wm + mt * 16 + (lane >> 2) + i * 8;
            int prow = grow % NN;
            float* crow = C + (size_t)grow * CC;
            const float* pr = pos + (size_t)prow * CC;
#pragma unroll
            for (int nq = 0; nq < 4; nq++) {
                int col = bn + wn + nq * 8 + (lane & 3) * 2;
                float2 o;
                o.x = acc[mt][nq][i * 2]     + bias[col];
                o.y = acc[mt][nq][i * 2 + 1] + bias[col + 1];
                if (addPos) { o.x += pr[col]; o.y += pr[col + 1]; }
                *(float2*)(crow + col) = o;
            }
        }
    }
#undef LOAD_STAGE2
}

// ======================= weight transpose + fp16 split (all 4 weights) ===
__global__ void wsplit_kernel(
    const float* __restrict__ W0, const float* __restrict__ W1,
    const float* __restrict__ W2, const float* __restrict__ W3,
    __half* __restrict__ Wh, __half* __restrict__ Wl)
{
    const float* W = (blockIdx.z == 0) ? W0 : (blockIdx.z == 1) ? W1 :
                     (blockIdx.z == 2) ? W2 : W3;
    size_t wo = (size_t)blockIdx.z * CC * CC;
    __shared__ float t[32][33];
    int n0 = blockIdx.x * 32, k0 = blockIdx.y * 32;
    int tx = threadIdx.x, ty = threadIdx.y;
#pragma unroll
    for (int i = 0; i < 4; i++)
        t[ty + 8 * i][tx] = W[(size_t)(k0 + ty + 8 * i) * CC + n0 + tx];
    __syncthreads();
#pragma unroll
    for (int i = 0; i < 4; i++) {
        float a = t[tx][ty + 8 * i];
        __half h = __float2half_rn(a);
        __half l = __float2half_rn(a - __half2float(h));
        size_t o = wo + (size_t)(n0 + ty + 8 * i) * CC + k0 + tx;
        Wh[o] = h; Wl[o] = l;
    }
}

// ======================= activation fp16 split (x only) =======================
__global__ __launch_bounds__(256) void split_kernel(
    const float4* __restrict__ A, __half2* __restrict__ Ah,
    __half2* __restrict__ Al, int n4)
{
    int i = blockIdx.x * 256 + threadIdx.x;
    if (i < n4) {
        float4 a = A[i];
        __half h0 = __float2half_rn(a.x);
        __half h1 = __float2half_rn(a.y);
        __half h2 = __float2half_rn(a.z);
        __half h3 = __float2half_rn(a.w);
        __half l0 = __float2half_rn(a.x - __half2float(h0));
        __half l1 = __float2half_rn(a.y - __half2float(h1));
        __half l2 = __float2half_rn(a.z - __half2float(h2));
        __half l3 = __float2half_rn(a.w - __half2float(h3));
        Ah[2 * i]     = __half2{h0, h1};
        Ah[2 * i + 1] = __half2{h2, h3};
        Al[2 * i]     = __half2{l0, l1};
        Al[2 * i + 1] = __half2{l2, l3};
    }
}

// ======================= inv softplus precompute =======================
__global__ void invsp_kernel(const float* __restrict__ sp)
{
    int c = blockIdx.x * 256 + threadIdx.x;
    if (c < CC) {
        float s = sp[c];
        float v = (s > 20.f) ? s : log1pf(expf(s));
        g_invsc[c] = 1.0f / v;
    }
}

// ======================= focusing kernel (float4, 192 thr) =======================
__global__ __launch_bounds__(192) void focus_kernel(float* __restrict__ q, float* __restrict__ k)
{
    float* t = blockIdx.y ? k : q;
    float4* p = (float4*)(t + (size_t)blockIdx.x * CC);
    const int tid = threadIdx.x;

    float4 x = p[tid];
    const float4 iv = ((const float4*)g_invsc)[tid];

    float v0 = (fmaxf(x.x, 0.f) + 1e-6f) * iv.x;
    float v1 = (fmaxf(x.y, 0.f) + 1e-6f) * iv.y;
    float v2 = (fmaxf(x.z, 0.f) + 1e-6f) * iv.z;
    float v3 = (fmaxf(x.w, 0.f) + 1e-6f) * iv.w;

    float a0 = v0 * v0, a1 = v1 * v1, a2 = v2 * v2, a3 = v3 * v3;
    float s2 = a0 + a1 + a2 + a3;
    float c0 = a0 * v0, c1 = a1 * v1, c2 = a2 * v2, c3 = a3 * v3;
    float s6 = c0 * c0 + c1 * c1 + c2 * c2 + c3 * c3;

    __shared__ float red2[6], red6[6];
    unsigned lane = tid & 31, w = tid >> 5;
#pragma unroll
    for (int o = 16; o > 0; o >>= 1) {
        s2 += __shfl_down_sync(0xffffffffu, s2, o);
        s6 += __shfl_down_sync(0xffffffffu, s6, o);
    }
    if (lane == 0) { red2[w] = s2; red6[w] = s6; }
    __syncthreads();
    float t2 = 0.f, t6 = 0.f;
#pragma unroll
    for (int i = 0; i < 6; i++) { t2 += red2[i]; t6 += red6[i]; }
    float f = sqrtf(t2 / t6);

    float4 o4;
    o4.x = c0 * f; o4.y = c1 * f; o4.z = c2 * f; o4.w = c3 * f;
    p[tid] = o4;
}

// ======================= fused kv + ksum + attn + dwc -> fp16 ==============
// grid (BHD, 2): block computes kv[:, ch0:ch0+48] itself (streamed K=196),
// ksum (full), then z + q@kv-half + dwc(v-half) -> fp16 ah.
#define FHC 48
// smem layout (float offsets)
#define F_KV   0                    // 96*48 = 4608
#define F_KSM  4608                 // 96
#define F_BS   4704                 // 48
#define F_WS   4752                 // 48*25 = 1200
#define F_R    5952                 // union region
#define F_KS1  F_R                  // phase1 k chunk: 28*96 = 2688
#define F_VS1  (F_R + 2688)         // phase1 v chunk: 28*49 = 1372
#define F_VF   F_R                  // phase2 v full: 196*49 = 9604
#define SMEM_F ((F_R + 9604) * 4)   // 62224 bytes

__global__ __launch_bounds__(256, 3) void fused_attn_kernel(
    const float* __restrict__ q, const float* __restrict__ k,
    const float* __restrict__ v, const float* __restrict__ w,
    const float* __restrict__ db, __half* __restrict__ ah)
{
    extern __shared__ float sm[];
    const int bh = blockIdx.x;
    const int b = bh >> 3, h = bh & 7;
    const int ch0 = blockIdx.y * FHC;
    const int tid = threadIdx.x;
    const int ty = tid >> 4;   // 0..15 -> 6 kv rows (c')
    const int tx = tid & 15;   // 0..15 -> 3 kv cols (d)

    // dwc weights/bias (separate smem region, loaded once)
    for (int idx = tid; idx < FHC * 25; idx += 256)
        sm[F_WS + idx] = w[ch0 * 25 + idx];
    if (tid < FHC) sm[F_BS + tid] = db[ch0 + tid];

    const float* kb = k + (size_t)b * NN * CC + h * HD;
    const float* vb = v + (size_t)b * NN * CC + h * HD + ch0;

    // ---------------- phase 1: kv-half + ksum ----------------
    float acc[6][3];
    float cs[6];
#pragma unroll
    for (int i = 0; i < 6; i++) {
        cs[i] = 0.f;
#pragma unroll
        for (int l = 0; l < 3; l++) acc[i][l] = 0.f;
    }

    for (int j0 = 0; j0 < NN; j0 += 28) {
        for (int idx = tid; idx < 28 * HD; idx += 256) {
            int j = idx / HD, c = idx % HD;
            sm[F_KS1 + j * HD + c] = kb[(size_t)(j0 + j) * CC + c];
        }
        for (int idx = tid; idx < 28 * FHC; idx += 256) {
            int j = idx / FHC, c = idx % FHC;
            sm[F_VS1 + j * (FHC + 1) + c] = vb[(size_t)(j0 + j) * CC + c];
        }
        __syncthreads();
#pragma unroll 4
        for (int j = 0; j < 28; j++) {
            float kf[6], vf[3];
            const float2* kp = (const float2*)(sm + F_KS1 + j * HD + ty * 6);
#pragma unroll
            for (int i = 0; i < 3; i++) {
                float2 k2 = kp[i];
                kf[2 * i] = k2.x; kf[2 * i + 1] = k2.y;
            }
#pragma unroll
            for (int l = 0; l < 3; l++)
                vf[l] = sm[F_VS1 + j * (FHC + 1) + tx * 3 + l];
            if (tx == 0) {
#pragma unroll
                for (int i = 0; i < 6; i++) cs[i] += kf[i];
            }
#pragma unroll
            for (int i = 0; i < 6; i++)
#pragma unroll
                for (int l = 0; l < 3; l++)
                    acc[i][l] = fmaf(kf[i], vf[l], acc[i][l]);
        }
        __syncthreads();
    }

    // park kv + ksum in smem
#pragma unroll
    for (int i = 0; i < 6; i++)
#pragma unroll
        for (int l = 0; l < 3; l++)
            sm[F_KV + (ty * 6 + i) * FHC + tx * 3 + l] = acc[i][l];
    if (tx == 0) {
#pragma unroll
        for (int i = 0; i < 6; i++) sm[F_KSM + ty * 6 + i] = cs[i];
    }
    __syncthreads();

    // ---------------- phase 2: load v-half full, attn + dwc ----------------
    for (int idx = tid; idx < NN * FHC; idx += 256) {
        int p = idx / FHC, c = idx % FHC;
        sm[F_VF + p * (FHC + 1) + c] = vb[(size_t)p * CC + c];
    }
    __syncthreads();

    if (tid < NN) {
        const float* qr = q + ((size_t)b * NN + tid) * CC + h * HD;
        float zi = 0.f;
#pragma unroll 8
        for (int c = 0; c < HD; c++) zi += qr[c] * sm[F_KSM + c];
        zi = 1.f / (zi + 1e-6f);

        float4 oacc[12];
#pragma unroll
        for (int d = 0; d < 12; d++) oacc[d] = make_float4(0.f, 0.f, 0.f, 0.f);

        for (int c = 0; c < HD; c++) {
            float qv = qr[c];
            const float4* kr = (const float4*)(sm + F_KV + c * FHC);
#pragma unroll
            for (int d = 0; d < 12; d++) {
                float4 k4 = kr[d];
                oacc[d].x = fmaf(qv, k4.x, oacc[d].x);
                oacc[d].y = fmaf(qv, k4.y, oacc[d].y);
                oacc[d].z = fmaf(qv, k4.z, oacc[d].z);
                oacc[d].w = fmaf(qv, k4.w, oacc[d].w);
            }
        }

        const int y = tid / 14, x = tid % 14;
        __half* orow = ah + ((size_t)b * NN + tid) * CC + h * HD + ch0;
#pragma unroll
        for (int d = 0; d < 12; d++) {
            float4 r = oacc[d];
            r.x *= zi; r.y *= zi; r.z *= zi; r.w *= zi;
            float* rp = (float*)&r;
#pragma unroll
            for (int e = 0; e < 4; e++) {
                int c = d * 4 + e;
                float s = sm[F_BS + c];
#pragma unroll
                for (int dy = -2; dy <= 2; dy++) {
                    int yy = y + dy;
                    if ((unsigned)yy >= 14u) continue;
#pragma unroll
                    for (int dx = -2; dx <= 2; dx++) {
                        int xx = x + dx;
                        if ((unsigned)xx >= 14u) continue;
                        s = fmaf(sm[F_WS + c * 25 + (dy + 2) * 5 + (dx + 2)],
                                 sm[F_VF + (yy * 14 + xx) * (FHC + 1) + c], s);
                    }
                }
                rp[e] += s;
            }
            *(__half2*)(orow + d * 4)     = __floats2half2_rn(r.x, r.y);
            *(__half2*)(orow + d * 4 + 2) = __floats2half2_rn(r.z, r.w);
        }
    }
}

// ======================= launch =======================
extern "C" void kernel_launch(void* const* d_in, const int* in_sizes, int n_in,
                              void* d_out, int out_size)
{
    const float* x   = (const float*)d_in[0];
    const float* Wq  = (const float*)d_in[1];
    const float* bq  = (const float*)d_in[2];
    const float* Wk  = (const float*)d_in[3];
    const float* bk  = (const float*)d_in[4];
    const float* Wv  = (const float*)d_in[5];
    const float* bv  = (const float*)d_in[6];
    const float* pos = (const float*)d_in[7];
    const float* sp  = (const float*)d_in[8];
    const float* dw  = (const float*)d_in[9];
    const float* db  = (const float*)d_in[10];
    const float* Wp  = (const float*)d_in[11];
    const float* bp  = (const float*)d_in[12];
    float* out = (float*)d_out;

    float *Q, *K, *V;
    __half *xh, *xl, *ah, *wh, *wl;
    cudaGetSymbolAddress((void**)&Q,  g_Q);
    cudaGetSymbolAddress((void**)&K,  g_K);
    cudaGetSymbolAddress((void**)&V,  g_V);
    cudaGetSymbolAddress((void**)&xh, g_xh);
    cudaGetSymbolAddress((void**)&xl, g_xl);
    cudaGetSymbolAddress((void**)&ah, g_ah);
    cudaGetSymbolAddress((void**)&wh, g_wh);
    cudaGetSymbolAddress((void**)&wl, g_wl);

    cudaFuncSetAttribute(gemm3_f16, cudaFuncAttributeMaxDynamicSharedMemorySize, SMEM_G3);
    cudaFuncSetAttribute(gemm2_f16, cudaFuncAttributeMaxDynamicSharedMemorySize, 3 * STGB);
    cudaFuncSetAttribute(fused_attn_kernel, cudaFuncAttributeMaxDynamicSharedMemorySize, SMEM_F);

    const size_t WSZ = (size_t)CC * CC;
    const int n4 = MROWS * CC / 4;

    // 0: weight transpose + split, 1: x split, 2: softplus reciprocal
    wsplit_kernel<<<dim3(24, 24, 4), dim3(32, 8)>>>(Wq, Wk, Wv, Wp, wh, wl);
    split_kernel<<<(n4 + 255) / 256, 256>>>((const float4*)x,
        (__half2*)xh, (__half2*)xl, n4);
    invsp_kernel<<<3, 256>>>(sp);

    dim3 gg3(CC / 256, MROWS / 128);   // (3, 196)
    dim3 gg2(CC / 128, MROWS / 128);   // (6, 196)
    // 3: Q (3-term), 4: K (3-term) — profiler control window
    gemm3_f16<<<gg3, 256, SMEM_G3>>>(xh, xl, wh + 0 * WSZ, wl + 0 * WSZ, bq, pos, Q, 0);
    gemm3_f16<<<gg3, 256, SMEM_G3>>>(xh, xl, wh + 1 * WSZ, wl + 1 * WSZ, bk, pos, K, 1);
    // 5: V (2-term)
    gemm2_f16<<<gg2, 256, 3 * STGB>>>(xh, wh + 2 * WSZ, wl + 2 * WSZ, bv, pos, V, 0);

    // 6: focusing
    focus_kernel<<<dim3(MROWS, 2), 192>>>(Q, K);

    // 7: fused kv + ksum + attn + dwc -> fp16 ah
    fused_attn_kernel<<<dim3(BHD, 2), 256, SMEM_F>>>(Q, K, V, dw, db, ah);

    // 8: output projection (2-term, reads ah directly)
    gemm2_f16<<<gg2, 256, 3 * STGB>>>(ah, wh + 3 * WSZ, wl + 3 * WSZ, bp, pos, out, 0);
}

// round 14
// speedup vs baseline: 1.0360x; 1.0360x over previous
#include <cuda_runtime.h>
#include <cuda_fp16.h>
#include <math.h>
#include <stdint.h>

// Problem constants
#define BB   128
#define NN   196
#define CC   768
#define HH   8
#define HD   96
#define MROWS (BB*NN)   // 25088
#define BHD   (BB*HH)   // 1024

// -------- device scratch (no runtime allocation allowed) --------
__device__ float g_Q[(size_t)MROWS*CC];
__device__ float g_K[(size_t)MROWS*CC];
__device__ float g_V[(size_t)MROWS*CC];
__device__ float g_KV[(size_t)BHD*HD*HD];
__device__ float g_KS[(size_t)BHD*HD];
__device__ float g_invsc[CC];
__device__ __half g_xh[(size_t)MROWS*CC];
__device__ __half g_xl[(size_t)MROWS*CC];
__device__ __half g_ah[(size_t)MROWS*CC];
__device__ __half g_wh[(size_t)4*CC*CC];
__device__ __half g_wl[(size_t)4*CC*CC];

// ======================= PTX helpers =======================
__device__ __forceinline__ uint32_t s2u(const void* p) {
    uint32_t a;
    asm("{ .reg .u64 t; cvta.to.shared.u64 t, %1; cvt.u32.u64 %0, t; }" : "=r"(a) : "l"(p));
    return a;
}

#define CP16(d, s) asm volatile("cp.async.cg.shared.global [%0], [%1], 16;" :: "r"(d), "l"(s))
#define CP_COMMIT() asm volatile("cp.async.commit_group;" ::: "memory")
#define CP_WAIT(n)  asm volatile("cp.async.wait_group %0;" :: "n"(n) : "memory")

#define LDSM4(r0, r1, r2, r3, a) \
    asm volatile("ldmatrix.sync.aligned.m8n8.x4.shared.b16 {%0,%1,%2,%3}, [%4];" \
        : "=r"(r0), "=r"(r1), "=r"(r2), "=r"(r3) : "r"(a))

#define MMA(dp, a, b0, b1) \
    asm volatile("mma.sync.aligned.m16n8k16.row.col.f32.f16.f16.f32 " \
        "{%0,%1,%2,%3},{%4,%5,%6,%7},{%8,%9},{%0,%1,%2,%3};" \
        : "+f"((dp)[0]), "+f"((dp)[1]), "+f"((dp)[2]), "+f"((dp)[3]) \
        : "r"((a)[0]), "r"((a)[1]), "r"((a)[2]), "r"((a)[3]), "r"(b0), "r"(b1))

// smem chunk swizzle: element row r (64B rows), 16B chunk c (0..3) -> byte offset
__device__ __forceinline__ uint32_t swoff(int r, int c) {
    return (uint32_t)(r * 64 + ((c ^ ((r >> 1) & 3)) << 4));
}

#define GITERS 24

// ======================= 3-term fp16 GEMM (measured 211us) =====
// D = Ah*Bh + Ah*Bl + Al*Bh + bias (+pos).
// CTA 128x256, warp 64x64, BK=32, 4-stage cp.async, 192KB smem, occ 1.
#define G3STGB 49152
#define G3AH   0
#define G3AL   8192
#define G3BH   16384
#define G3BL   32768
#define SMEM_G3 (4*G3STGB)  // 196608

__global__ __launch_bounds__(256, 1) void gemm3_f16(
    const __half* __restrict__ Ah, const __half* __restrict__ Al,
    const __half* __restrict__ Bh, const __half* __restrict__ Bl,
    const float* __restrict__ bias, const float* __restrict__ pos,
    float* __restrict__ C, int addPos)
{
    extern __shared__ char smem[];
    const uint32_t sb = s2u(smem);
    const int tid  = threadIdx.x;
    const int lane = tid & 31;
    const int wid  = tid >> 5;
    const int wm   = (wid & 1) * 64;
    const int wn   = (wid >> 1) * 64;
    const int bm   = blockIdx.y * 128;
    const int bn   = blockIdx.x * 256;

#define LOAD_STAGE3(s, kit) do {                                              \
    int k0 = (kit) * 32;                                                      \
    uint32_t st = sb + (uint32_t)(s) * G3STGB;                                \
    _Pragma("unroll")                                                         \
    for (int i = 0; i < 2; i++) {                                             \
        int u = i * 256 + tid; int r = u >> 2, c = u & 3;                     \
        uint32_t so = swoff(r, c);                                            \
        size_t go = (size_t)(bm + r) * CC + k0 + c * 8;                       \
        CP16(st + G3AH + so, Ah + go);                                        \
        CP16(st + G3AL + so, Al + go);                                        \
    }                                                                         \
    _Pragma("unroll")                                                         \
    for (int i = 0; i < 4; i++) {                                             \
        int u = i * 256 + tid; int r = u >> 2, c = u & 3;                     \
        uint32_t so = swoff(r, c);                                            \
        size_t go = (size_t)(bn + r) * CC + k0 + c * 8;                       \
        CP16(st + G3BH + so, Bh + go);                                        \
        CP16(st + G3BL + so, Bl + go);                                        \
    }                                                                         \
    CP_COMMIT();                                                              \
} while (0)

    float acc[4][8][4];
#pragma unroll
    for (int a = 0; a < 4; a++)
#pragma unroll
        for (int b = 0; b < 8; b++)
#pragma unroll
            for (int c = 0; c < 4; c++) acc[a][b][c] = 0.f;

    LOAD_STAGE3(0, 0);
    LOAD_STAGE3(1, 1);
    LOAD_STAGE3(2, 2);

    const int arow = lane & 15;
    const int achk = lane >> 4;
    const int brow = (lane & 7) + ((lane >> 4) & 1) * 8;
    const int bchk = (lane >> 3) & 1;

    for (int it = 0; it < GITERS; ++it) {
        int rem = GITERS - 1 - it;
        if (rem >= 2) { CP_WAIT(2); }
        else if (rem == 1) { CP_WAIT(1); }
        else { CP_WAIT(0); }
        __syncthreads();

        int ld = it + 3;
        if (ld < GITERS) LOAD_STAGE3(ld & 3, ld);

        uint32_t st = sb + (uint32_t)(it & 3) * G3STGB;
#pragma unroll
        for (int kk = 0; kk < 2; kk++) {
            uint32_t ahf[4][4], alf[4][4];
#pragma unroll
            for (int mt = 0; mt < 4; mt++) {
                int row = wm + mt * 16 + arow;
                uint32_t off = swoff(row, kk * 2 + achk);
                LDSM4(ahf[mt][0], ahf[mt][1], ahf[mt][2], ahf[mt][3], st + G3AH + off);
                LDSM4(alf[mt][0], alf[mt][1], alf[mt][2], alf[mt][3], st + G3AL + off);
            }
#pragma unroll
            for (int bq = 0; bq < 4; bq++) {
                int row = wn + bq * 16 + brow;
                uint32_t off = swoff(row, kk * 2 + bchk);
                uint32_t bh0, bh1, bh2, bh3, bl0, bl1, bl2, bl3;
                LDSM4(bh0, bh1, bh2, bh3, st + G3BH + off);
                LDSM4(bl0, bl1, bl2, bl3, st + G3BL + off);
#pragma unroll
                for (int mt = 0; mt < 4; mt++) {
                    MMA(acc[mt][bq * 2],     ahf[mt], bh0, bh1);
                    MMA(acc[mt][bq * 2],     ahf[mt], bl0, bl1);
                    MMA(acc[mt][bq * 2],     alf[mt], bh0, bh1);
                    MMA(acc[mt][bq * 2 + 1], ahf[mt], bh2, bh3);
                    MMA(acc[mt][bq * 2 + 1], ahf[mt], bl2, bl3);
                    MMA(acc[mt][bq * 2 + 1], alf[mt], bh2, bh3);
                }
            }
        }
    }

#pragma unroll
    for (int mt = 0; mt < 4; mt++) {
#pragma unroll
        for (int i = 0; i < 2; i++) {
            int grow = bm + wm + mt * 16 + (lane >> 2) + i * 8;
            int prow = grow % NN;
            float* crow = C + (size_t)grow * CC;
            const float* pr = pos + (size_t)prow * CC;
#pragma unroll
            for (int nq = 0; nq < 8; nq++) {
                int col = bn + wn + nq * 8 + (lane & 3) * 2;
                float2 o;
                o.x = acc[mt][nq][i * 2]     + bias[col];
                o.y = acc[mt][nq][i * 2 + 1] + bias[col + 1];
                if (addPos) { o.x += pr[col]; o.y += pr[col + 1]; }
                *(float2*)(crow + col) = o;
            }
        }
    }
#undef LOAD_STAGE3
}

// ======================= 2-term fp16 GEMM (measured 146us) =================
// D = Ah*(Bh+Bl) + bias (+pos).  CTA 128x128, warp 64x32, BK=32, 3 stages, occ 2.
#define STGB   32768
#define OAH    0
#define OBH    16384
#define OBL    24576

__global__ __launch_bounds__(256, 2) void gemm2_f16(
    const __half* __restrict__ Ah,
    const __half* __restrict__ Bh, const __half* __restrict__ Bl,
    const float* __restrict__ bias, const float* __restrict__ pos,
    float* __restrict__ C, int addPos)
{
    extern __shared__ char smem[];
    const uint32_t sb = s2u(smem);
    const int tid  = threadIdx.x;
    const int lane = tid & 31;
    const int wid  = tid >> 5;
    const int wm   = (wid & 1) * 64;
    const int wn   = (wid >> 1) * 32;
    const int bm   = blockIdx.y * 128;
    const int bn   = blockIdx.x * 128;

#define LOAD_STAGE2(s, kit) do {                                              \
    int k0 = (kit) * 32;                                                      \
    uint32_t st = sb + (uint32_t)(s) * STGB;                                  \
    _Pragma("unroll")                                                         \
    for (int i = 0; i < 2; i++) {                                             \
        int u = i * 256 + tid; int r = u >> 2, c = u & 3;                     \
        uint32_t so = swoff(r, c);                                            \
        size_t ga = (size_t)(bm + r) * CC + k0 + c * 8;                       \
        size_t gb = (size_t)(bn + r) * CC + k0 + c * 8;                       \
        CP16(st + OAH + so, Ah + ga);                                         \
        CP16(st + OBH + so, Bh + gb);                                         \
        CP16(st + OBL + so, Bl + gb);                                         \
    }                                                                         \
    CP_COMMIT();                                                              \
} while (0)

    float acc[4][4][4];
#pragma unroll
    for (int a = 0; a < 4; a++)
#pragma unroll
        for (int b = 0; b < 4; b++)
#pragma unroll
            for (int c = 0; c < 4; c++) acc[a][b][c] = 0.f;

    LOAD_STAGE2(0, 0);
    LOAD_STAGE2(1, 1);

    const int arow = lane & 15;
    const int achk = lane >> 4;
    const int brow = (lane & 7) + ((lane >> 4) & 1) * 8;
    const int bchk = (lane >> 3) & 1;

    int slot = 0;
    for (int it = 0; it < GITERS; ++it) {
        if (it == GITERS - 1) { CP_WAIT(0); } else { CP_WAIT(1); }
        __syncthreads();

        int ld = it + 2;
        if (ld < GITERS) {
            int ls = slot + 2; if (ls >= 3) ls -= 3;
            LOAD_STAGE2(ls, ld);
        }

        uint32_t st = sb + (uint32_t)slot * STGB;
#pragma unroll
        for (int kk = 0; kk < 2; kk++) {
            uint32_t ahf[4][4];
#pragma unroll
            for (int mt = 0; mt < 4; mt++) {
                int row = wm + mt * 16 + arow;
                uint32_t off = swoff(row, kk * 2 + achk);
                LDSM4(ahf[mt][0], ahf[mt][1], ahf[mt][2], ahf[mt][3], st + OAH + off);
            }
#pragma unroll
            for (int g = 0; g < 2; g++) {
                int row = wn + g * 16 + brow;
                uint32_t off = swoff(row, kk * 2 + bchk);
                uint32_t bh0, bh1, bh2, bh3, bl0, bl1, bl2, bl3;
                LDSM4(bh0, bh1, bh2, bh3, st + OBH + off);
                LDSM4(bl0, bl1, bl2, bl3, st + OBL + off);
#pragma unroll
                for (int mt = 0; mt < 4; mt++) {
                    MMA(acc[mt][g * 2],     ahf[mt], bh0, bh1);
                    MMA(acc[mt][g * 2],     ahf[mt], bl0, bl1);
                    MMA(acc[mt][g * 2 + 1], ahf[mt], bh2, bh3);
                    MMA(acc[mt][g * 2 + 1], ahf[mt], bl2, bl3);
                }
            }
        }
        if (++slot >= 3) slot = 0;
    }

#pragma unroll
    for (int mt = 0; mt < 4; mt++) {
#pragma unroll
        for (int i = 0; i < 2; i++) {
            int grow = bm + wm + mt * 16 + (lane >> 2) + i * 8;
            int prow = grow % NN;
            float* crow = C + (size_t)grow * CC;
            const float* pr = pos + (size_t)prow * CC;
#pragma unroll
            for (int nq = 0; nq < 4; nq++) {
                int col = bn + wn + nq * 8 + (lane & 3) * 2;
                float2 o;
                o.x = acc[mt][nq][i * 2]     + bias[col];
                o.y = acc[mt][nq][i * 2 + 1] + bias[col + 1];
                if (addPos) { o.x += pr[col]; o.y += pr[col + 1]; }
                *(float2*)(crow + col) = o;
            }
        }
    }
#undef LOAD_STAGE2
}

// ======================= weight transpose + fp16 split (all 4 weights) ===
__global__ void wsplit_kernel(
    const float* __restrict__ W0, const float* __restrict__ W1,
    const float* __restrict__ W2, const float* __restrict__ W3,
    __half* __restrict__ Wh, __half* __restrict__ Wl)
{
    const float* W = (blockIdx.z == 0) ? W0 : (blockIdx.z == 1) ? W1 :
                     (blockIdx.z == 2) ? W2 : W3;
    size_t wo = (size_t)blockIdx.z * CC * CC;
    __shared__ float t[32][33];
    int n0 = blockIdx.x * 32, k0 = blockIdx.y * 32;
    int tx = threadIdx.x, ty = threadIdx.y;
#pragma unroll
    for (int i = 0; i < 4; i++)
        t[ty + 8 * i][tx] = W[(size_t)(k0 + ty + 8 * i) * CC + n0 + tx];
    __syncthreads();
#pragma unroll
    for (int i = 0; i < 4; i++) {
        float a = t[tx][ty + 8 * i];
        __half h = __float2half_rn(a);
        __half l = __float2half_rn(a - __half2float(h));
        size_t o = wo + (size_t)(n0 + ty + 8 * i) * CC + k0 + tx;
        Wh[o] = h; Wl[o] = l;
    }
}

// ======================= activation fp16 split (x only) =======================
__global__ __launch_bounds__(256) void split_kernel(
    const float4* __restrict__ A, __half2* __restrict__ Ah,
    __half2* __restrict__ Al, int n4)
{
    int i = blockIdx.x * 256 + threadIdx.x;
    if (i < n4) {
        float4 a = A[i];
        __half h0 = __float2half_rn(a.x);
        __half h1 = __float2half_rn(a.y);
        __half h2 = __float2half_rn(a.z);
        __half h3 = __float2half_rn(a.w);
        __half l0 = __float2half_rn(a.x - __half2float(h0));
        __half l1 = __float2half_rn(a.y - __half2float(h1));
        __half l2 = __float2half_rn(a.z - __half2float(h2));
        __half l3 = __float2half_rn(a.w - __half2float(h3));
        Ah[2 * i]     = __half2{h0, h1};
        Ah[2 * i + 1] = __half2{h2, h3};
        Al[2 * i]     = __half2{l0, l1};
        Al[2 * i + 1] = __half2{l2, l3};
    }
}

// ======================= inv softplus precompute =======================
__global__ void invsp_kernel(const float* __restrict__ sp)
{
    int c = blockIdx.x * 256 + threadIdx.x;
    if (c < CC) {
        float s = sp[c];
        float v = (s > 20.f) ? s : log1pf(expf(s));
        g_invsc[c] = 1.0f / v;
    }
}

// ======================= focusing kernel (warp-per-row) =======================
// block: 256 thr = 8 warps = 8 rows; grid (MROWS/8, 2).  No smem, shfl-only.
__global__ __launch_bounds__(256) void focus_kernel(float* __restrict__ q, float* __restrict__ k)
{
    float* t = blockIdx.y ? k : q;
    const int w    = threadIdx.x >> 5;
    const int lane = threadIdx.x & 31;
    const size_t row = (size_t)blockIdx.x * 8 + w;
    float4* p = (float4*)(t + row * CC);

    float4 r[6];
    float vv[24];
    float s2 = 0.f, s6 = 0.f;
#pragma unroll
    for (int i = 0; i < 6; i++) {
        float4 x  = p[lane + i * 32];
        const float4 iv = ((const float4*)g_invsc)[lane + i * 32];
        float v0 = (fmaxf(x.x, 0.f) + 1e-6f) * iv.x;
        float v1 = (fmaxf(x.y, 0.f) + 1e-6f) * iv.y;
        float v2 = (fmaxf(x.z, 0.f) + 1e-6f) * iv.z;
        float v3 = (fmaxf(x.w, 0.f) + 1e-6f) * iv.w;
        float a0 = v0 * v0, a1 = v1 * v1, a2 = v2 * v2, a3 = v3 * v3;
        s2 += a0 + a1 + a2 + a3;
        float c0 = a0 * v0, c1 = a1 * v1, c2 = a2 * v2, c3 = a3 * v3;
        s6 += c0 * c0 + c1 * c1 + c2 * c2 + c3 * c3;
        vv[i * 4 + 0] = c0; vv[i * 4 + 1] = c1;
        vv[i * 4 + 2] = c2; vv[i * 4 + 3] = c3;
        r[i] = x; // keep register pressure sane; r unused further
    }
    (void)r;

#pragma unroll
    for (int o = 16; o > 0; o >>= 1) {
        s2 += __shfl_xor_sync(0xffffffffu, s2, o);
        s6 += __shfl_xor_sync(0xffffffffu, s6, o);
    }
    float f = sqrtf(s2 / s6);

#pragma unroll
    for (int i = 0; i < 6; i++) {
        float4 o4;
        o4.x = vv[i * 4 + 0] * f;
        o4.y = vv[i * 4 + 1] * f;
        o4.z = vv[i * 4 + 2] * f;
        o4.w = vv[i * 4 + 3] * f;
        p[lane + i * 32] = o4;
    }
}

// ======================= kv = k^T v per (b,h), ksum fused, float2 LDS ======
__global__ __launch_bounds__(256) void kv_kernel(
    const float* __restrict__ k, const float* __restrict__ v,
    float* __restrict__ kv, float* __restrict__ ksum)
{
    int bh = blockIdx.x;
    int b = bh >> 3, h = bh & 7;
    __shared__ float ks[28][HD];
    __shared__ float vs[28][HD];
    const int tid = threadIdx.x;
    const int ty = tid >> 4;
    const int tx = tid & 15;

    float acc[6][6];
    float cs[6];
#pragma unroll
    for (int i = 0; i < 6; i++) {
        cs[i] = 0.f;
#pragma unroll
        for (int j = 0; j < 6; j++) acc[i][j] = 0.f;
    }

    const float* kb = k + (size_t)b * NN * CC + h * HD;
    const float* vb = v + (size_t)b * NN * CC + h * HD;

    for (int j0 = 0; j0 < NN; j0 += 28) {
        for (int idx = tid; idx < 28 * HD; idx += 256) {
            int j = idx / HD, c = idx % HD;
            ks[j][c] = kb[(size_t)(j0 + j) * CC + c];
            vs[j][c] = vb[(size_t)(j0 + j) * CC + c];
        }
        __syncthreads();
#pragma unroll 7
        for (int j = 0; j < 28; j++) {
            float kf[6], vf[6];
            const float2* kp = (const float2*)(&ks[j][ty * 6]);
            const float2* vp = (const float2*)(&vs[j][tx * 6]);
#pragma unroll
            for (int i = 0; i < 3; i++) {
                float2 k2 = kp[i];
                kf[2 * i] = k2.x; kf[2 * i + 1] = k2.y;
                float2 v2 = vp[i];
                vf[2 * i] = v2.x; vf[2 * i + 1] = v2.y;
            }
            if (tx == 0) {
#pragma unroll
                for (int i = 0; i < 6; i++) cs[i] += kf[i];
            }
#pragma unroll
            for (int i = 0; i < 6; i++)
#pragma unroll
                for (int l = 0; l < 6; l++)
                    acc[i][l] = fmaf(kf[i], vf[l], acc[i][l]);
        }
        __syncthreads();
    }

#pragma unroll
    for (int i = 0; i < 6; i++)
#pragma unroll
        for (int l = 0; l < 6; l++)
            kv[(size_t)bh * HD * HD + (ty * 6 + i) * HD + tx * 6 + l] = acc[i][l];
    if (tx == 0) {
#pragma unroll
        for (int i = 0; i < 6; i++)
            ksum[bh * HD + ty * 6 + i] = cs[i];
    }
}

// ======================= fused attention-out + dwc -> fp16, channel-split ==
#define HC 48
#define SM_KV2   0
#define SM_KSM2  (HD*HC)
#define SM_WS2   (SM_KSM2 + HD)
#define SM_BS2   (SM_WS2 + HC*25)
#define SM_VS2   (SM_BS2 + HC)
#define SMEM_AD  ((SM_VS2 + NN*(HC+1)) * 4)

__global__ __launch_bounds__(224, 3) void attn_dwc_kernel(
    const float* __restrict__ q, const float* __restrict__ kv,
    const float* __restrict__ ksum, const float* __restrict__ v,
    const float* __restrict__ w, const float* __restrict__ db,
    __half* __restrict__ ah)
{
    extern __shared__ float sm[];
    int bh = blockIdx.x;
    int b = bh >> 3, h = bh & 7;
    int ch0 = blockIdx.y * HC;
    const int tid = threadIdx.x;

    for (int idx = tid; idx < HD * HC; idx += 224) {
        int c = idx / HC, d = idx % HC;
        sm[SM_KV2 + idx] = kv[(size_t)bh * HD * HD + c * HD + ch0 + d];
    }
    for (int idx = tid; idx < NN * HC; idx += 224) {
        int p = idx / HC, c = idx % HC;
        sm[SM_VS2 + p * (HC + 1) + c] = v[((size_t)b * NN + p) * CC + h * HD + ch0 + c];
    }
    for (int idx = tid; idx < HC * 25; idx += 224)
        sm[SM_WS2 + idx] = w[ch0 * 25 + idx];
    if (tid < HD) sm[SM_KSM2 + tid] = ksum[bh * HD + tid];
    if (tid < HC) sm[SM_BS2 + tid] = db[ch0 + tid];
    __syncthreads();

    if (tid < NN) {
        const float* qr = q + ((size_t)b * NN + tid) * CC + h * HD;
        float zi = 0.f;
#pragma unroll 8
        for (int c = 0; c < HD; c++) zi += qr[c] * sm[SM_KSM2 + c];
        zi = 1.f / (zi + 1e-6f);

        float4 acc[12];
#pragma unroll
        for (int d = 0; d < 12; d++) acc[d] = make_float4(0.f, 0.f, 0.f, 0.f);

        for (int c = 0; c < HD; c++) {
            float qv = qr[c];
            const float4* kr = (const float4*)(sm + SM_KV2 + c * HC);
#pragma unroll
            for (int d = 0; d < 12; d++) {
                float4 k4 = kr[d];
                acc[d].x = fmaf(qv, k4.x, acc[d].x);
                acc[d].y = fmaf(qv, k4.y, acc[d].y);
                acc[d].z = fmaf(qv, k4.z, acc[d].z);
                acc[d].w = fmaf(qv, k4.w, acc[d].w);
            }
        }

        const int y = tid / 14, x = tid % 14;
        __half* orow = ah + ((size_t)b * NN + tid) * CC + h * HD + ch0;
#pragma unroll
        for (int d = 0; d < 12; d++) {
            float4 r = acc[d];
            r.x *= zi; r.y *= zi; r.z *= zi; r.w *= zi;
            float* rp = (float*)&r;
#pragma unroll
            for (int e = 0; e < 4; e++) {
                int c = d * 4 + e;
                float s = sm[SM_BS2 + c];
#pragma unroll
                for (int dy = -2; dy <= 2; dy++) {
                    int yy = y + dy;
                    if ((unsigned)yy >= 14u) continue;
#pragma unroll
                    for (int dx = -2; dx <= 2; dx++) {
                        int xx = x + dx;
                        if ((unsigned)xx >= 14u) continue;
                        s = fmaf(sm[SM_WS2 + c * 25 + (dy + 2) * 5 + (dx + 2)],
                                 sm[SM_VS2 + (yy * 14 + xx) * (HC + 1) + c], s);
                    }
                }
                rp[e] += s;
            }
            *(__half2*)(orow + d * 4)     = __floats2half2_rn(r.x, r.y);
            *(__half2*)(orow + d * 4 + 2) = __floats2half2_rn(r.z, r.w);
        }
    }
}

// ======================= launch =======================
extern "C" void kernel_launch(void* const* d_in, const int* in_sizes, int n_in,
                              void* d_out, int out_size)
{
    const float* x   = (const float*)d_in[0];
    const float* Wq  = (const float*)d_in[1];
    const float* bq  = (const float*)d_in[2];
    const float* Wk  = (const float*)d_in[3];
    const float* bk  = (const float*)d_in[4];
    const float* Wv  = (const float*)d_in[5];
    const float* bv  = (const float*)d_in[6];
    const float* pos = (const float*)d_in[7];
    const float* sp  = (const float*)d_in[8];
    const float* dw  = (const float*)d_in[9];
    const float* db  = (const float*)d_in[10];
    const float* Wp  = (const float*)d_in[11];
    const float* bp  = (const float*)d_in[12];
    float* out = (float*)d_out;

    float *Q, *K, *V, *KV, *KS;
    __half *xh, *xl, *ah, *wh, *wl;
    cudaGetSymbolAddress((void**)&Q,  g_Q);
    cudaGetSymbolAddress((void**)&K,  g_K);
    cudaGetSymbolAddress((void**)&V,  g_V);
    cudaGetSymbolAddress((void**)&KV, g_KV);
    cudaGetSymbolAddress((void**)&KS, g_KS);
    cudaGetSymbolAddress((void**)&xh, g_xh);
    cudaGetSymbolAddress((void**)&xl, g_xl);
    cudaGetSymbolAddress((void**)&ah, g_ah);
    cudaGetSymbolAddress((void**)&wh, g_wh);
    cudaGetSymbolAddress((void**)&wl, g_wl);

    cudaFuncSetAttribute(gemm3_f16, cudaFuncAttributeMaxDynamicSharedMemorySize, SMEM_G3);
    cudaFuncSetAttribute(gemm2_f16, cudaFuncAttributeMaxDynamicSharedMemorySize, 3 * STGB);
    cudaFuncSetAttribute(attn_dwc_kernel, cudaFuncAttributeMaxDynamicSharedMemorySize, SMEM_AD);

    const size_t WSZ = (size_t)CC * CC;
    const int n4 = MROWS * CC / 4;

    // 0: weight transpose + split, 1: x split, 2: softplus reciprocal
    wsplit_kernel<<<dim3(24, 24, 4), dim3(32, 8)>>>(Wq, Wk, Wv, Wp, wh, wl);
    split_kernel<<<(n4 + 255) / 256, 256>>>((const float4*)x,
        (__half2*)xh, (__half2*)xl, n4);
    invsp_kernel<<<3, 256>>>(sp);

    dim3 gg3(CC / 256, MROWS / 128);   // (3, 196)
    dim3 gg2(CC / 128, MROWS / 128);   // (6, 196)
    // 3: Q (3-term), 4: K (3-term) — profiler control window
    gemm3_f16<<<gg3, 256, SMEM_G3>>>(xh, xl, wh + 0 * WSZ, wl + 0 * WSZ, bq, pos, Q, 0);
    gemm3_f16<<<gg3, 256, SMEM_G3>>>(xh, xl, wh + 1 * WSZ, wl + 1 * WSZ, bk, pos, K, 1);
    // 5: V (2-term)
    gemm2_f16<<<gg2, 256, 3 * STGB>>>(xh, wh + 2 * WSZ, wl + 2 * WSZ, bv, pos, V, 0);

    // 6: focusing (warp-per-row)
    focus_kernel<<<dim3(MROWS / 8, 2), 256>>>(Q, K);

    // 7: kv + ksum, 8: attn-out + dwc -> fp16 ah (channel-split)
    kv_kernel<<<BHD, 256>>>(K, V, KV, KS);
    attn_dwc_kernel<<<dim3(BHD, 2), 224, SMEM_AD>>>(Q, KV, KS, V, dw, db, ah);

    // 9: output projection (2-term, reads ah directly)
    gemm2_f16<<<gg2, 256, 3 * STGB>>>(ah, wh + 3 * WSZ, wl + 3 * WSZ, bp, pos, out, 0);
}

// round 15
// speedup vs baseline: 1.0701x; 1.0329x over previous
#include <cuda_runtime.h>
#include <cuda_fp16.h>
#include <math.h>
#include <stdint.h>

// Problem constants
#define BB   128
#define NN   196
#define CC   768
#define HH   8
#define HD   96
#define MROWS (BB*NN)   // 25088
#define BHD   (BB*HH)   // 1024

// -------- device scratch (no runtime allocation allowed) --------
__device__ float g_Q[(size_t)MROWS*CC];
__device__ float g_K[(size_t)MROWS*CC];
__device__ float g_V[(size_t)MROWS*CC];
__device__ float g_KV[(size_t)BHD*HD*HD];
__device__ float g_KS[(size_t)BHD*HD];
__device__ float g_invsc[CC];
__device__ __half g_xh[(size_t)MROWS*CC];
__device__ __half g_xl[(size_t)MROWS*CC];
__device__ __half g_ah[(size_t)MROWS*CC];
__device__ __half g_wh[(size_t)4*CC*CC];
__device__ __half g_wl[(size_t)4*CC*CC];

// ======================= PTX helpers =======================
__device__ __forceinline__ uint32_t s2u(const void* p) {
    uint32_t a;
    asm("{ .reg .u64 t; cvta.to.shared.u64 t, %1; cvt.u32.u64 %0, t; }" : "=r"(a) : "l"(p));
    return a;
}

#define CP16(d, s) asm volatile("cp.async.cg.shared.global [%0], [%1], 16;" :: "r"(d), "l"(s))
#define CP_COMMIT() asm volatile("cp.async.commit_group;" ::: "memory")
#define CP_WAIT(n)  asm volatile("cp.async.wait_group %0;" :: "n"(n) : "memory")

#define LDSM4(r0, r1, r2, r3, a) \
    asm volatile("ldmatrix.sync.aligned.m8n8.x4.shared.b16 {%0,%1,%2,%3}, [%4];" \
        : "=r"(r0), "=r"(r1), "=r"(r2), "=r"(r3) : "r"(a))

#define MMA(dp, a, b0, b1) \
    asm volatile("mma.sync.aligned.m16n8k16.row.col.f32.f16.f16.f32 " \
        "{%0,%1,%2,%3},{%4,%5,%6,%7},{%8,%9},{%0,%1,%2,%3};" \
        : "+f"((dp)[0]), "+f"((dp)[1]), "+f"((dp)[2]), "+f"((dp)[3]) \
        : "r"((a)[0]), "r"((a)[1]), "r"((a)[2]), "r"((a)[3]), "r"(b0), "r"(b1))

// packed fp32x2 helpers (Blackwell base-arch PTX)
__device__ __forceinline__ uint64_t d2(float a, float b) {
    uint64_t r; asm("mov.b64 %0, {%1,%2};" : "=l"(r) : "f"(a), "f"(b)); return r;
}
__device__ __forceinline__ float2 u2(uint64_t v) {
    float lo, hi; asm("mov.b64 {%0,%1}, %2;" : "=f"(lo), "=f"(hi) : "l"(v));
    return make_float2(lo, hi);
}
#define FMA2(d, a, b)  asm("fma.rn.f32x2 %0, %1, %2, %0;" : "+l"(d) : "l"(a), "l"(b))
#define FMA2S(d, m, a) asm("fma.rn.f32x2 %0, %0, %1, %2;" : "+l"(d) : "l"(m), "l"(a))

// smem chunk swizzle: element row r (64B rows), 16B chunk c (0..3) -> byte offset
__device__ __forceinline__ uint32_t swoff(int r, int c) {
    return (uint32_t)(r * 64 + ((c ^ ((r >> 1) & 3)) << 4));
}

#define GITERS 24

// ======================= 3-term fp16 GEMM (measured 211us) =====
#define G3STGB 49152
#define G3AH   0
#define G3AL   8192
#define G3BH   16384
#define G3BL   32768
#define SMEM_G3 (4*G3STGB)  // 196608

__global__ __launch_bounds__(256, 1) void gemm3_f16(
    const __half* __restrict__ Ah, const __half* __restrict__ Al,
    const __half* __restrict__ Bh, const __half* __restrict__ Bl,
    const float* __restrict__ bias, const float* __restrict__ pos,
    float* __restrict__ C, int addPos)
{
    extern __shared__ char smem[];
    const uint32_t sb = s2u(smem);
    const int tid  = threadIdx.x;
    const int lane = tid & 31;
    const int wid  = tid >> 5;
    const int wm   = (wid & 1) * 64;
    const int wn   = (wid >> 1) * 64;
    const int bm   = blockIdx.y * 128;
    const int bn   = blockIdx.x * 256;

#define LOAD_STAGE3(s, kit) do {                                              \
    int k0 = (kit) * 32;                                                      \
    uint32_t st = sb + (uint32_t)(s) * G3STGB;                                \
    _Pragma("unroll")                                                         \
    for (int i = 0; i < 2; i++) {                                             \
        int u = i * 256 + tid; int r = u >> 2, c = u & 3;                     \
        uint32_t so = swoff(r, c);                                            \
        size_t go = (size_t)(bm + r) * CC + k0 + c * 8;                       \
        CP16(st + G3AH + so, Ah + go);                                        \
        CP16(st + G3AL + so, Al + go);                                        \
    }                                                                         \
    _Pragma("unroll")                                                         \
    for (int i = 0; i < 4; i++) {                                             \
        int u = i * 256 + tid; int r = u >> 2, c = u & 3;                     \
        uint32_t so = swoff(r, c);                                            \
        size_t go = (size_t)(bn + r) * CC + k0 + c * 8;                       \
        CP16(st + G3BH + so, Bh + go);                                        \
        CP16(st + G3BL + so, Bl + go);                                        \
    }                                                                         \
    CP_COMMIT();                                                              \
} while (0)

    float acc[4][8][4];
#pragma unroll
    for (int a = 0; a < 4; a++)
#pragma unroll
        for (int b = 0; b < 8; b++)
#pragma unroll
            for (int c = 0; c < 4; c++) acc[a][b][c] = 0.f;

    LOAD_STAGE3(0, 0);
    LOAD_STAGE3(1, 1);
    LOAD_STAGE3(2, 2);

    const int arow = lane & 15;
    const int achk = lane >> 4;
    const int brow = (lane & 7) + ((lane >> 4) & 1) * 8;
    const int bchk = (lane >> 3) & 1;

    for (int it = 0; it < GITERS; ++it) {
        int rem = GITERS - 1 - it;
        if (rem >= 2) { CP_WAIT(2); }
        else if (rem == 1) { CP_WAIT(1); }
        else { CP_WAIT(0); }
        __syncthreads();

        int ld = it + 3;
        if (ld < GITERS) LOAD_STAGE3(ld & 3, ld);

        uint32_t st = sb + (uint32_t)(it & 3) * G3STGB;
#pragma unroll
        for (int kk = 0; kk < 2; kk++) {
            uint32_t ahf[4][4], alf[4][4];
#pragma unroll
            for (int mt = 0; mt < 4; mt++) {
                int row = wm + mt * 16 + arow;
                uint32_t off = swoff(row, kk * 2 + achk);
                LDSM4(ahf[mt][0], ahf[mt][1], ahf[mt][2], ahf[mt][3], st + G3AH + off);
                LDSM4(alf[mt][0], alf[mt][1], alf[mt][2], alf[mt][3], st + G3AL + off);
            }
#pragma unroll
            for (int bq = 0; bq < 4; bq++) {
                int row = wn + bq * 16 + brow;
                uint32_t off = swoff(row, kk * 2 + bchk);
                uint32_t bh0, bh1, bh2, bh3, bl0, bl1, bl2, bl3;
                LDSM4(bh0, bh1, bh2, bh3, st + G3BH + off);
                LDSM4(bl0, bl1, bl2, bl3, st + G3BL + off);
#pragma unroll
                for (int mt = 0; mt < 4; mt++) {
                    MMA(acc[mt][bq * 2],     ahf[mt], bh0, bh1);
                    MMA(acc[mt][bq * 2],     ahf[mt], bl0, bl1);
                    MMA(acc[mt][bq * 2],     alf[mt], bh0, bh1);
                    MMA(acc[mt][bq * 2 + 1], ahf[mt], bh2, bh3);
                    MMA(acc[mt][bq * 2 + 1], ahf[mt], bl2, bl3);
                    MMA(acc[mt][bq * 2 + 1], alf[mt], bh2, bh3);
                }
            }
        }
    }

#pragma unroll
    for (int mt = 0; mt < 4; mt++) {
#pragma unroll
        for (int i = 0; i < 2; i++) {
            int grow = bm + wm + mt * 16 + (lane >> 2) + i * 8;
            int prow = grow % NN;
            float* crow = C + (size_t)grow * CC;
            const float* pr = pos + (size_t)prow * CC;
#pragma unroll
            for (int nq = 0; nq < 8; nq++) {
                int col = bn + wn + nq * 8 + (lane & 3) * 2;
                float2 o;
                o.x = acc[mt][nq][i * 2]     + bias[col];
                o.y = acc[mt][nq][i * 2 + 1] + bias[col + 1];
                if (addPos) { o.x += pr[col]; o.y += pr[col + 1]; }
                *(float2*)(crow + col) = o;
            }
        }
    }
#undef LOAD_STAGE3
}

// ======================= 2-term fp16 GEMM (measured 146us) =================
#define STGB   32768
#define OAH    0
#define OBH    16384
#define OBL    24576

__global__ __launch_bounds__(256, 2) void gemm2_f16(
    const __half* __restrict__ Ah,
    const __half* __restrict__ Bh, const __half* __restrict__ Bl,
    const float* __restrict__ bias, const float* __restrict__ pos,
    float* __restrict__ C, int addPos)
{
    extern __shared__ char smem[];
    const uint32_t sb = s2u(smem);
    const int tid  = threadIdx.x;
    const int lane = tid & 31;
    const int wid  = tid >> 5;
    const int wm   = (wid & 1) * 64;
    const int wn   = (wid >> 1) * 32;
    const int bm   = blockIdx.y * 128;
    const int bn   = blockIdx.x * 128;

#define LOAD_STAGE2(s, kit) do {                                              \
    int k0 = (kit) * 32;                                                      \
    uint32_t st = sb + (uint32_t)(s) * STGB;                                  \
    _Pragma("unroll")                                                         \
    for (int i = 0; i < 2; i++) {                                             \
        int u = i * 256 + tid; int r = u >> 2, c = u & 3;                     \
        uint32_t so = swoff(r, c);                                            \
        size_t ga = (size_t)(bm + r) * CC + k0 + c * 8;                       \
        size_t gb = (size_t)(bn + r) * CC + k0 + c * 8;                       \
        CP16(st + OAH + so, Ah + ga);                                         \
        CP16(st + OBH + so, Bh + gb);                                         \
        CP16(st + OBL + so, Bl + gb);                                         \
    }                                                                         \
    CP_COMMIT();                                                              \
} while (0)

    float acc[4][4][4];
#pragma unroll
    for (int a = 0; a < 4; a++)
#pragma unroll
        for (int b = 0; b < 4; b++)
#pragma unroll
            for (int c = 0; c < 4; c++) acc[a][b][c] = 0.f;

    LOAD_STAGE2(0, 0);
    LOAD_STAGE2(1, 1);

    const int arow = lane & 15;
    const int achk = lane >> 4;
    const int brow = (lane & 7) + ((lane >> 4) & 1) * 8;
    const int bchk = (lane >> 3) & 1;

    int slot = 0;
    for (int it = 0; it < GITERS; ++it) {
        if (it == GITERS - 1) { CP_WAIT(0); } else { CP_WAIT(1); }
        __syncthreads();

        int ld = it + 2;
        if (ld < GITERS) {
            int ls = slot + 2; if (ls >= 3) ls -= 3;
            LOAD_STAGE2(ls, ld);
        }

        uint32_t st = sb + (uint32_t)slot * STGB;
#pragma unroll
        for (int kk = 0; kk < 2; kk++) {
            uint32_t ahf[4][4];
#pragma unroll
            for (int mt = 0; mt < 4; mt++) {
                int row = wm + mt * 16 + arow;
                uint32_t off = swoff(row, kk * 2 + achk);
                LDSM4(ahf[mt][0], ahf[mt][1], ahf[mt][2], ahf[mt][3], st + OAH + off);
            }
#pragma unroll
            for (int g = 0; g < 2; g++) {
                int row = wn + g * 16 + brow;
                uint32_t off = swoff(row, kk * 2 + bchk);
                uint32_t bh0, bh1, bh2, bh3, bl0, bl1, bl2, bl3;
                LDSM4(bh0, bh1, bh2, bh3, st + OBH + off);
                LDSM4(bl0, bl1, bl2, bl3, st + OBL + off);
#pragma unroll
                for (int mt = 0; mt < 4; mt++) {
                    MMA(acc[mt][g * 2],     ahf[mt], bh0, bh1);
                    MMA(acc[mt][g * 2],     ahf[mt], bl0, bl1);
                    MMA(acc[mt][g * 2 + 1], ahf[mt], bh2, bh3);
                    MMA(acc[mt][g * 2 + 1], ahf[mt], bl2, bl3);
                }
            }
        }
        if (++slot >= 3) slot = 0;
    }

#pragma unroll
    for (int mt = 0; mt < 4; mt++) {
#pragma unroll
        for (int i = 0; i < 2; i++) {
            int grow = bm + wm + mt * 16 + (lane >> 2) + i * 8;
            int prow = grow % NN;
            float* crow = C + (size_t)grow * CC;
            const float* pr = pos + (size_t)prow * CC;
#pragma unroll
            for (int nq = 0; nq < 4; nq++) {
                int col = bn + wn + nq * 8 + (lane & 3) * 2;
                float2 o;
                o.x = acc[mt][nq][i * 2]     + bias[col];
                o.y = acc[mt][nq][i * 2 + 1] + bias[col + 1];
                if (addPos) { o.x += pr[col]; o.y += pr[col + 1]; }
                *(float2*)(crow + col) = o;
            }
        }
    }
#undef LOAD_STAGE2
}

// ======================= weight transpose + fp16 split (all 4 weights) ===
__global__ void wsplit_kernel(
    const float* __restrict__ W0, const float* __restrict__ W1,
    const float* __restrict__ W2, const float* __restrict__ W3,
    __half* __restrict__ Wh, __half* __restrict__ Wl)
{
    const float* W = (blockIdx.z == 0) ? W0 : (blockIdx.z == 1) ? W1 :
                     (blockIdx.z == 2) ? W2 : W3;
    size_t wo = (size_t)blockIdx.z * CC * CC;
    __shared__ float t[32][33];
    int n0 = blockIdx.x * 32, k0 = blockIdx.y * 32;
    int tx = threadIdx.x, ty = threadIdx.y;
#pragma unroll
    for (int i = 0; i < 4; i++)
        t[ty + 8 * i][tx] = W[(size_t)(k0 + ty + 8 * i) * CC + n0 + tx];
    __syncthreads();
#pragma unroll
    for (int i = 0; i < 4; i++) {
        float a = t[tx][ty + 8 * i];
        __half h = __float2half_rn(a);
        __half l = __float2half_rn(a - __half2float(h));
        size_t o = wo + (size_t)(n0 + ty + 8 * i) * CC + k0 + tx;
        Wh[o] = h; Wl[o] = l;
    }
}

// ======================= activation fp16 split (x only) =======================
__global__ __launch_bounds__(256) void split_kernel(
    const float4* __restrict__ A, __half2* __restrict__ Ah,
    __half2* __restrict__ Al, int n4)
{
    int i = blockIdx.x * 256 + threadIdx.x;
    if (i < n4) {
        float4 a = A[i];
        __half h0 = __float2half_rn(a.x);
        __half h1 = __float2half_rn(a.y);
        __half h2 = __float2half_rn(a.z);
        __half h3 = __float2half_rn(a.w);
        __half l0 = __float2half_rn(a.x - __half2float(h0));
        __half l1 = __float2half_rn(a.y - __half2float(h1));
        __half l2 = __float2half_rn(a.z - __half2float(h2));
        __half l3 = __float2half_rn(a.w - __half2float(h3));
        Ah[2 * i]     = __half2{h0, h1};
        Ah[2 * i + 1] = __half2{h2, h3};
        Al[2 * i]     = __half2{l0, l1};
        Al[2 * i + 1] = __half2{l2, l3};
    }
}

// ======================= inv softplus precompute =======================
__global__ void invsp_kernel(const float* __restrict__ sp)
{
    int c = blockIdx.x * 256 + threadIdx.x;
    if (c < CC) {
        float s = sp[c];
        float v = (s > 20.f) ? s : log1pf(expf(s));
        g_invsc[c] = 1.0f / v;
    }
}

// ======================= focusing kernel (warp-per-row) =======================
__global__ __launch_bounds__(256) void focus_kernel(float* __restrict__ q, float* __restrict__ k)
{
    float* t = blockIdx.y ? k : q;
    const int w    = threadIdx.x >> 5;
    const int lane = threadIdx.x & 31;
    const size_t row = (size_t)blockIdx.x * 8 + w;
    float4* p = (float4*)(t + row * CC);

    float vv[24];
    float s2 = 0.f, s6 = 0.f;
#pragma unroll
    for (int i = 0; i < 6; i++) {
        float4 x  = p[lane + i * 32];
        const float4 iv = ((const float4*)g_invsc)[lane + i * 32];
        float v0 = (fmaxf(x.x, 0.f) + 1e-6f) * iv.x;
        float v1 = (fmaxf(x.y, 0.f) + 1e-6f) * iv.y;
        float v2 = (fmaxf(x.z, 0.f) + 1e-6f) * iv.z;
        float v3 = (fmaxf(x.w, 0.f) + 1e-6f) * iv.w;
        float a0 = v0 * v0, a1 = v1 * v1, a2 = v2 * v2, a3 = v3 * v3;
        s2 += a0 + a1 + a2 + a3;
        float c0 = a0 * v0, c1 = a1 * v1, c2 = a2 * v2, c3 = a3 * v3;
        s6 += c0 * c0 + c1 * c1 + c2 * c2 + c3 * c3;
        vv[i * 4 + 0] = c0; vv[i * 4 + 1] = c1;
        vv[i * 4 + 2] = c2; vv[i * 4 + 3] = c3;
    }

#pragma unroll
    for (int o = 16; o > 0; o >>= 1) {
        s2 += __shfl_xor_sync(0xffffffffu, s2, o);
        s6 += __shfl_xor_sync(0xffffffffu, s6, o);
    }
    float f = sqrtf(s2 / s6);

#pragma unroll
    for (int i = 0; i < 6; i++) {
        float4 o4;
        o4.x = vv[i * 4 + 0] * f;
        o4.y = vv[i * 4 + 1] * f;
        o4.z = vv[i * 4 + 2] * f;
        o4.w = vv[i * 4 + 3] * f;
        p[lane + i * 32] = o4;
    }
}

// ======================= kv = k^T v per (b,h), ksum fused, f32x2 ===========
__global__ __launch_bounds__(256) void kv_kernel(
    const float* __restrict__ k, const float* __restrict__ v,
    float* __restrict__ kv, float* __restrict__ ksum)
{
    int bh = blockIdx.x;
    int b = bh >> 3, h = bh & 7;
    __shared__ float ks[28][HD];
    __shared__ float vs[28][HD];
    const int tid = threadIdx.x;
    const int ty = tid >> 4;
    const int tx = tid & 15;

    uint64_t acc2[6][3];
    float cs[6];
#pragma unroll
    for (int i = 0; i < 6; i++) {
        cs[i] = 0.f;
#pragma unroll
        for (int l = 0; l < 3; l++) acc2[i][l] = 0ull;
    }

    const float* kb = k + (size_t)b * NN * CC + h * HD;
    const float* vb = v + (size_t)b * NN * CC + h * HD;

    for (int j0 = 0; j0 < NN; j0 += 28) {
        for (int idx = tid; idx < 28 * HD; idx += 256) {
            int j = idx / HD, c = idx % HD;
            ks[j][c] = kb[(size_t)(j0 + j) * CC + c];
            vs[j][c] = vb[(size_t)(j0 + j) * CC + c];
        }
        __syncthreads();
#pragma unroll 7
        for (int j = 0; j < 28; j++) {
            const float2* kp = (const float2*)(&ks[j][ty * 6]);
            float2 k01 = kp[0], k23 = kp[1], k45 = kp[2];
            uint64_t kd[6];
            kd[0] = d2(k01.x, k01.x); kd[1] = d2(k01.y, k01.y);
            kd[2] = d2(k23.x, k23.x); kd[3] = d2(k23.y, k23.y);
            kd[4] = d2(k45.x, k45.x); kd[5] = d2(k45.y, k45.y);
            const uint64_t* vp = (const uint64_t*)(&vs[j][tx * 6]);
            uint64_t v0 = vp[0], v1 = vp[1], v2 = vp[2];
            if (tx == 0) {
                cs[0] += k01.x; cs[1] += k01.y;
                cs[2] += k23.x; cs[3] += k23.y;
                cs[4] += k45.x; cs[5] += k45.y;
            }
#pragma unroll
            for (int i = 0; i < 6; i++) {
                FMA2(acc2[i][0], kd[i], v0);
                FMA2(acc2[i][1], kd[i], v1);
                FMA2(acc2[i][2], kd[i], v2);
            }
        }
        __syncthreads();
    }

#pragma unroll
    for (int i = 0; i < 6; i++)
#pragma unroll
        for (int l = 0; l < 3; l++) {
            float2 pr = u2(acc2[i][l]);
            *(float2*)(kv + (size_t)bh * HD * HD + (ty * 6 + i) * HD + tx * 6 + l * 2) = pr;
        }
    if (tx == 0) {
#pragma unroll
        for (int i = 0; i < 6; i++)
            ksum[bh * HD + ty * 6 + i] = cs[i];
    }
}

// ======================= attention-out + dwc -> fp16, channel-split, f32x2 ==
#define HC 48
#define VST 50   // padded v row stride (even -> 8B aligned float2)
#define SM_KV2   0
#define SM_KSM2  (HD*HC)
#define SM_WS2   (SM_KSM2 + HD)       // tap-major: [tap][c], 25*48
#define SM_BS2   (SM_WS2 + 25*HC)
#define SM_VS2   (SM_BS2 + HC)
#define SMEM_AD  ((SM_VS2 + NN*VST) * 4)

__global__ __launch_bounds__(224, 3) void attn_dwc_kernel(
    const float* __restrict__ q, const float* __restrict__ kv,
    const float* __restrict__ ksum, const float* __restrict__ v,
    const float* __restrict__ w, const float* __restrict__ db,
    __half* __restrict__ ah)
{
    extern __shared__ float sm[];
    int bh = blockIdx.x;
    int b = bh >> 3, h = bh & 7;
    int ch0 = blockIdx.y * HC;
    const int tid = threadIdx.x;

    for (int idx = tid; idx < HD * HC; idx += 224) {
        int c = idx / HC, d = idx % HC;
        sm[SM_KV2 + idx] = kv[(size_t)bh * HD * HD + c * HD + ch0 + d];
    }
    for (int idx = tid; idx < NN * HC; idx += 224) {
        int p = idx / HC, c = idx % HC;
        sm[SM_VS2 + p * VST + c] = v[((size_t)b * NN + p) * CC + h * HD + ch0 + c];
    }
    // dwc weights tap-major: sm[SM_WS2 + tap*48 + c] = w[(ch0+c)*25 + tap]
    for (int idx = tid; idx < 25 * HC; idx += 224) {
        int tap = idx / HC, c = idx % HC;
        sm[SM_WS2 + idx] = w[(ch0 + c) * 25 + tap];
    }
    if (tid < HD) sm[SM_KSM2 + tid] = ksum[bh * HD + tid];
    if (tid < HC) sm[SM_BS2 + tid] = db[ch0 + tid];
    __syncthreads();

    if (tid < NN) {
        const float* qr = q + ((size_t)b * NN + tid) * CC + h * HD;
        float zi = 0.f;
#pragma unroll 8
        for (int c = 0; c < HD; c++) zi += qr[c] * sm[SM_KSM2 + c];
        zi = 1.f / (zi + 1e-6f);

        uint64_t acc2[24];
#pragma unroll
        for (int d = 0; d < 24; d++) acc2[d] = 0ull;

        for (int c = 0; c < HD; c++) {
            uint64_t qd = d2(qr[c], qr[c]);
            const uint64_t* kr = (const uint64_t*)(sm + SM_KV2 + c * HC);
#pragma unroll
            for (int d = 0; d < 24; d++) FMA2(acc2[d], qd, kr[d]);
        }

        // acc = acc*zi + bias
        {
            uint64_t zd = d2(zi, zi);
            const uint64_t* bs = (const uint64_t*)(sm + SM_BS2);
#pragma unroll
            for (int d = 0; d < 24; d++) FMA2S(acc2[d], zd, bs[d]);
        }

        // dwc taps accumulate into acc
        const int y = tid / 14, x = tid % 14;
#pragma unroll
        for (int dy = -2; dy <= 2; dy++) {
            int yy = y + dy;
            if ((unsigned)yy >= 14u) continue;
#pragma unroll
            for (int dx = -2; dx <= 2; dx++) {
                int xx = x + dx;
                if ((unsigned)xx >= 14u) continue;
                int tap = (dy + 2) * 5 + (dx + 2);
                const uint64_t* wr = (const uint64_t*)(sm + SM_WS2 + tap * HC);
                const uint64_t* vr = (const uint64_t*)(sm + SM_VS2 + (yy * 14 + xx) * VST);
#pragma unroll
                for (int d = 0; d < 24; d++) FMA2(acc2[d], wr[d], vr[d]);
            }
        }

        __half* orow = ah + ((size_t)b * NN + tid) * CC + h * HD + ch0;
#pragma unroll
        for (int d = 0; d < 24; d++) {
            float2 r = u2(acc2[d]);
            *(__half2*)(orow + d * 2) = __floats2half2_rn(r.x, r.y);
        }
    }
}

// ======================= launch =======================
extern "C" void kernel_launch(void* const* d_in, const int* in_sizes, int n_in,
                              void* d_out, int out_size)
{
    const float* x   = (const float*)d_in[0];
    const float* Wq  = (const float*)d_in[1];
    const float* bq  = (const float*)d_in[2];
    const float* Wk  = (const float*)d_in[3];
    const float* bk  = (const float*)d_in[4];
    const float* Wv  = (const float*)d_in[5];
    const float* bv  = (const float*)d_in[6];
    const float* pos = (const float*)d_in[7];
    const float* sp  = (const float*)d_in[8];
    const float* dw  = (const float*)d_in[9];
    const float* db  = (const float*)d_in[10];
    const float* Wp  = (const float*)d_in[11];
    const float* bp  = (const float*)d_in[12];
    float* out = (float*)d_out;

    float *Q, *K, *V, *KV, *KS;
    __half *xh, *xl, *ah, *wh, *wl;
    cudaGetSymbolAddress((void**)&Q,  g_Q);
    cudaGetSymbolAddress((void**)&K,  g_K);
    cudaGetSymbolAddress((void**)&V,  g_V);
    cudaGetSymbolAddress((void**)&KV, g_KV);
    cudaGetSymbolAddress((void**)&KS, g_KS);
    cudaGetSymbolAddress((void**)&xh, g_xh);
    cudaGetSymbolAddress((void**)&xl, g_xl);
    cudaGetSymbolAddress((void**)&ah, g_ah);
    cudaGetSymbolAddress((void**)&wh, g_wh);
    cudaGetSymbolAddress((void**)&wl, g_wl);

    cudaFuncSetAttribute(gemm3_f16, cudaFuncAttributeMaxDynamicSharedMemorySize, SMEM_G3);
    cudaFuncSetAttribute(gemm2_f16, cudaFuncAttributeMaxDynamicSharedMemorySize, 3 * STGB);
    cudaFuncSetAttribute(attn_dwc_kernel, cudaFuncAttributeMaxDynamicSharedMemorySize, SMEM_AD);

    const size_t WSZ = (size_t)CC * CC;
    const int n4 = MROWS * CC / 4;

    // 0: weight transpose + split, 1: x split, 2: softplus reciprocal
    wsplit_kernel<<<dim3(24, 24, 4), dim3(32, 8)>>>(Wq, Wk, Wv, Wp, wh, wl);
    split_kernel<<<(n4 + 255) / 256, 256>>>((const float4*)x,
        (__half2*)xh, (__half2*)xl, n4);
    invsp_kernel<<<3, 256>>>(sp);

    dim3 gg3(CC / 256, MROWS / 128);   // (3, 196)
    dim3 gg2(CC / 128, MROWS / 128);   // (6, 196)
    // 3: Q (3-term), 4: K (3-term) — profiler control window
    gemm3_f16<<<gg3, 256, SMEM_G3>>>(xh, xl, wh + 0 * WSZ, wl + 0 * WSZ, bq, pos, Q, 0);
    gemm3_f16<<<gg3, 256, SMEM_G3>>>(xh, xl, wh + 1 * WSZ, wl + 1 * WSZ, bk, pos, K, 1);
    // 5: V (2-term)
    gemm2_f16<<<gg2, 256, 3 * STGB>>>(xh, wh + 2 * WSZ, wl + 2 * WSZ, bv, pos, V, 0);

    // 6: focusing (warp-per-row)
    focus_kernel<<<dim3(MROWS / 8, 2), 256>>>(Q, K);

    // 7: kv + ksum (f32x2), 8: attn-out + dwc -> fp16 ah (f32x2)
    kv_kernel<<<BHD, 256>>>(K, V, KV, KS);
    attn_dwc_kernel<<<dim3(BHD, 2), 224, SMEM_AD>>>(Q, KV, KS, V, dw, db, ah);

    // 9: output projection (2-term, reads ah directly)
    gemm2_f16<<<gg2, 256, 3 * STGB>>>(ah, wh + 3 * WSZ, wl + 3 * WSZ, bp, pos, out, 0);
}

// round 16
// speedup vs baseline: 1.1958x; 1.1175x over previous
#include <cuda_runtime.h>
#include <cuda_fp16.h>
#include <math.h>
#include <stdint.h>

// Problem constants
#define BB   128
#define NN   196
#define CC   768
#define HH   8
#define HD   96
#define MROWS (BB*NN)   // 25088
#define BHD   (BB*HH)   // 1024

// -------- device scratch (no runtime allocation allowed) --------
__device__ float g_Q[(size_t)MROWS*CC];
__device__ float g_K[(size_t)MROWS*CC];
__device__ float g_V[(size_t)MROWS*CC];
__device__ float g_KV[(size_t)BHD*HD*HD];
__device__ float g_KS[(size_t)BHD*HD];
__device__ float g_invsc[CC];
__device__ __half g_xh[(size_t)MROWS*CC];
__device__ __half g_xl[(size_t)MROWS*CC];
__device__ __half g_ah[(size_t)MROWS*CC];
__device__ __half g_wh[(size_t)4*CC*CC];
__device__ __half g_wl[(size_t)4*CC*CC];

// ======================= PTX helpers =======================
__device__ __forceinline__ uint32_t s2u(const void* p) {
    uint32_t a;
    asm("{ .reg .u64 t; cvta.to.shared.u64 t, %1; cvt.u32.u64 %0, t; }" : "=r"(a) : "l"(p));
    return a;
}

#define CP16(d, s) asm volatile("cp.async.cg.shared.global [%0], [%1], 16;" :: "r"(d), "l"(s))
#define CP_COMMIT() asm volatile("cp.async.commit_group;" ::: "memory")
#define CP_WAIT(n)  asm volatile("cp.async.wait_group %0;" :: "n"(n) : "memory")

#define LDSM4(r0, r1, r2, r3, a) \
    asm volatile("ldmatrix.sync.aligned.m8n8.x4.shared.b16 {%0,%1,%2,%3}, [%4];" \
        : "=r"(r0), "=r"(r1), "=r"(r2), "=r"(r3) : "r"(a))

#define MMA(dp, a, b0, b1) \
    asm volatile("mma.sync.aligned.m16n8k16.row.col.f32.f16.f16.f32 " \
        "{%0,%1,%2,%3},{%4,%5,%6,%7},{%8,%9},{%0,%1,%2,%3};" \
        : "+f"((dp)[0]), "+f"((dp)[1]), "+f"((dp)[2]), "+f"((dp)[3]) \
        : "r"((a)[0]), "r"((a)[1]), "r"((a)[2]), "r"((a)[3]), "r"(b0), "r"(b1))

// packed fp32x2 helpers (Blackwell base-arch PTX)
__device__ __forceinline__ uint64_t d2(float a, float b) {
    uint64_t r; asm("mov.b64 %0, {%1,%2};" : "=l"(r) : "f"(a), "f"(b)); return r;
}
__device__ __forceinline__ float2 u2(uint64_t v) {
    float lo, hi; asm("mov.b64 {%0,%1}, %2;" : "=f"(lo), "=f"(hi) : "l"(v));
    return make_float2(lo, hi);
}
#define FMA2(d, a, b)  asm("fma.rn.f32x2 %0, %1, %2, %0;" : "+l"(d) : "l"(a), "l"(b))
#define FMA2S(d, m, a) asm("fma.rn.f32x2 %0, %0, %1, %2;" : "+l"(d) : "l"(m), "l"(a))

// smem chunk swizzle: element row r (64B rows), 16B chunk c (0..3) -> byte offset
__device__ __forceinline__ uint32_t swoff(int r, int c) {
    return (uint32_t)(r * 64 + ((c ^ ((r >> 1) & 3)) << 4));
}

#define GITERS 24

// ======================= 3-term fp16 GEMM (measured 210us) =====
#define G3STGB 49152
#define G3AH   0
#define G3AL   8192
#define G3BH   16384
#define G3BL   32768
#define SMEM_G3 (4*G3STGB)  // 196608

__global__ __launch_bounds__(256, 1) void gemm3_f16(
    const __half* __restrict__ Ah, const __half* __restrict__ Al,
    const __half* __restrict__ Bh, const __half* __restrict__ Bl,
    const float* __restrict__ bias, const float* __restrict__ pos,
    float* __restrict__ C, int addPos)
{
    extern __shared__ char smem[];
    const uint32_t sb = s2u(smem);
    const int tid  = threadIdx.x;
    const int lane = tid & 31;
    const int wid  = tid >> 5;
    const int wm   = (wid & 1) * 64;
    const int wn   = (wid >> 1) * 64;
    const int bm   = blockIdx.y * 128;
    const int bn   = blockIdx.x * 256;

#define LOAD_STAGE3(s, kit) do {                                              \
    int k0 = (kit) * 32;                                                      \
    uint32_t st = sb + (uint32_t)(s) * G3STGB;                                \
    _Pragma("unroll")                                                         \
    for (int i = 0; i < 2; i++) {                                             \
        int u = i * 256 + tid; int r = u >> 2, c = u & 3;                     \
        uint32_t so = swoff(r, c);                                            \
        size_t go = (size_t)(bm + r) * CC + k0 + c * 8;                       \
        CP16(st + G3AH + so, Ah + go);                                        \
        CP16(st + G3AL + so, Al + go);                                        \
    }                                                                         \
    _Pragma("unroll")                                                         \
    for (int i = 0; i < 4; i++) {                                             \
        int u = i * 256 + tid; int r = u >> 2, c = u & 3;                     \
        uint32_t so = swoff(r, c);                                            \
        size_t go = (size_t)(bn + r) * CC + k0 + c * 8;                       \
        CP16(st + G3BH + so, Bh + go);                                        \
        CP16(st + G3BL + so, Bl + go);                                        \
    }                                                                         \
    CP_COMMIT();                                                              \
} while (0)

    float acc[4][8][4];
#pragma unroll
    for (int a = 0; a < 4; a++)
#pragma unroll
        for (int b = 0; b < 8; b++)
#pragma unroll
            for (int c = 0; c < 4; c++) acc[a][b][c] = 0.f;

    LOAD_STAGE3(0, 0);
    LOAD_STAGE3(1, 1);
    LOAD_STAGE3(2, 2);

    const int arow = lane & 15;
    const int achk = lane >> 4;
    const int brow = (lane & 7) + ((lane >> 4) & 1) * 8;
    const int bchk = (lane >> 3) & 1;

    for (int it = 0; it < GITERS; ++it) {
        int rem = GITERS - 1 - it;
        if (rem >= 2) { CP_WAIT(2); }
        else if (rem == 1) { CP_WAIT(1); }
        else { CP_WAIT(0); }
        __syncthreads();

        int ld = it + 3;
        if (ld < GITERS) LOAD_STAGE3(ld & 3, ld);

        uint32_t st = sb + (uint32_t)(it & 3) * G3STGB;
#pragma unroll
        for (int kk = 0; kk < 2; kk++) {
            uint32_t ahf[4][4], alf[4][4];
#pragma unroll
            for (int mt = 0; mt < 4; mt++) {
                int row = wm + mt * 16 + arow;
                uint32_t off = swoff(row, kk * 2 + achk);
                LDSM4(ahf[mt][0], ahf[mt][1], ahf[mt][2], ahf[mt][3], st + G3AH + off);
                LDSM4(alf[mt][0], alf[mt][1], alf[mt][2], alf[mt][3], st + G3AL + off);
            }
#pragma unroll
            for (int bq = 0; bq < 4; bq++) {
                int row = wn + bq * 16 + brow;
                uint32_t off = swoff(row, kk * 2 + bchk);
                uint32_t bh0, bh1, bh2, bh3, bl0, bl1, bl2, bl3;
                LDSM4(bh0, bh1, bh2, bh3, st + G3BH + off);
                LDSM4(bl0, bl1, bl2, bl3, st + G3BL + off);
#pragma unroll
                for (int mt = 0; mt < 4; mt++) {
                    MMA(acc[mt][bq * 2],     ahf[mt], bh0, bh1);
                    MMA(acc[mt][bq * 2],     ahf[mt], bl0, bl1);
                    MMA(acc[mt][bq * 2],     alf[mt], bh0, bh1);
                    MMA(acc[mt][bq * 2 + 1], ahf[mt], bh2, bh3);
                    MMA(acc[mt][bq * 2 + 1], ahf[mt], bl2, bl3);
                    MMA(acc[mt][bq * 2 + 1], alf[mt], bh2, bh3);
                }
            }
        }
    }

#pragma unroll
    for (int mt = 0; mt < 4; mt++) {
#pragma unroll
        for (int i = 0; i < 2; i++) {
            int grow = bm + wm + mt * 16 + (lane >> 2) + i * 8;
            int prow = grow % NN;
            float* crow = C + (size_t)grow * CC;
            const float* pr = pos + (size_t)prow * CC;
#pragma unroll
            for (int nq = 0; nq < 8; nq++) {
                int col = bn + wn + nq * 8 + (lane & 3) * 2;
                float2 o;
                o.x = acc[mt][nq][i * 2]     + bias[col];
                o.y = acc[mt][nq][i * 2 + 1] + bias[col + 1];
                if (addPos) { o.x += pr[col]; o.y += pr[col + 1]; }
                *(float2*)(crow + col) = o;
            }
        }
    }
#undef LOAD_STAGE3
}

// ======================= 2-term fp16 GEMM (measured 146us) =================
#define STGB   32768
#define OAH    0
#define OBH    16384
#define OBL    24576

__global__ __launch_bounds__(256, 2) void gemm2_f16(
    const __half* __restrict__ Ah,
    const __half* __restrict__ Bh, const __half* __restrict__ Bl,
    const float* __restrict__ bias, const float* __restrict__ pos,
    float* __restrict__ C, int addPos)
{
    extern __shared__ char smem[];
    const uint32_t sb = s2u(smem);
    const int tid  = threadIdx.x;
    const int lane = tid & 31;
    const int wid  = tid >> 5;
    const int wm   = (wid & 1) * 64;
    const int wn   = (wid >> 1) * 32;
    const int bm   = blockIdx.y * 128;
    const int bn   = blockIdx.x * 128;

#define LOAD_STAGE2(s, kit) do {                                              \
    int k0 = (kit) * 32;                                                      \
    uint32_t st = sb + (uint32_t)(s) * STGB;                                  \
    _Pragma("unroll")                                                         \
    for (int i = 0; i < 2; i++) {                                             \
        int u = i * 256 + tid; int r = u >> 2, c = u & 3;                     \
        uint32_t so = swoff(r, c);                                            \
        size_t ga = (size_t)(bm + r) * CC + k0 + c * 8;                       \
        size_t gb = (size_t)(bn + r) * CC + k0 + c * 8;                       \
        CP16(st + OAH + so, Ah + ga);                                         \
        CP16(st + OBH + so, Bh + gb);                                         \
        CP16(st + OBL + so, Bl + gb);                                         \
    }                                                                         \
    CP_COMMIT();                                                              \
} while (0)

    float acc[4][4][4];
#pragma unroll
    for (int a = 0; a < 4; a++)
#pragma unroll
        for (int b = 0; b < 4; b++)
#pragma unroll
            for (int c = 0; c < 4; c++) acc[a][b][c] = 0.f;

    LOAD_STAGE2(0, 0);
    LOAD_STAGE2(1, 1);

    const int arow = lane & 15;
    const int achk = lane >> 4;
    const int brow = (lane & 7) + ((lane >> 4) & 1) * 8;
    const int bchk = (lane >> 3) & 1;

    int slot = 0;
    for (int it = 0; it < GITERS; ++it) {
        if (it == GITERS - 1) { CP_WAIT(0); } else { CP_WAIT(1); }
        __syncthreads();

        int ld = it + 2;
        if (ld < GITERS) {
            int ls = slot + 2; if (ls >= 3) ls -= 3;
            LOAD_STAGE2(ls, ld);
        }

        uint32_t st = sb + (uint32_t)slot * STGB;
#pragma unroll
        for (int kk = 0; kk < 2; kk++) {
            uint32_t ahf[4][4];
#pragma unroll
            for (int mt = 0; mt < 4; mt++) {
                int row = wm + mt * 16 + arow;
                uint32_t off = swoff(row, kk * 2 + achk);
                LDSM4(ahf[mt][0], ahf[mt][1], ahf[mt][2], ahf[mt][3], st + OAH + off);
            }
#pragma unroll
            for (int g = 0; g < 2; g++) {
                int row = wn + g * 16 + brow;
                uint32_t off = swoff(row, kk * 2 + bchk);
                uint32_t bh0, bh1, bh2, bh3, bl0, bl1, bl2, bl3;
                LDSM4(bh0, bh1, bh2, bh3, st + OBH + off);
                LDSM4(bl0, bl1, bl2, bl3, st + OBL + off);
#pragma unroll
                for (int mt = 0; mt < 4; mt++) {
                    MMA(acc[mt][g * 2],     ahf[mt], bh0, bh1);
                    MMA(acc[mt][g * 2],     ahf[mt], bl0, bl1);
                    MMA(acc[mt][g * 2 + 1], ahf[mt], bh2, bh3);
                    MMA(acc[mt][g * 2 + 1], ahf[mt], bl2, bl3);
                }
            }
        }
        if (++slot >= 3) slot = 0;
    }

#pragma unroll
    for (int mt = 0; mt < 4; mt++) {
#pragma unroll
        for (int i = 0; i < 2; i++) {
            int grow = bm + wm + mt * 16 + (lane >> 2) + i * 8;
            int prow = grow % NN;
            float* crow = C + (size_t)grow * CC;
            const float* pr = pos + (size_t)prow * CC;
#pragma unroll
            for (int nq = 0; nq < 4; nq++) {
                int col = bn + wn + nq * 8 + (lane & 3) * 2;
                float2 o;
                o.x = acc[mt][nq][i * 2]     + bias[col];
                o.y = acc[mt][nq][i * 2 + 1] + bias[col + 1];
                if (addPos) { o.x += pr[col]; o.y += pr[col + 1]; }
                *(float2*)(crow + col) = o;
            }
        }
    }
#undef LOAD_STAGE2
}

// ======================= weight transpose + fp16 split (all 4 weights) ===
__global__ void wsplit_kernel(
    const float* __restrict__ W0, const float* __restrict__ W1,
    const float* __restrict__ W2, const float* __restrict__ W3,
    __half* __restrict__ Wh, __half* __restrict__ Wl)
{
    const float* W = (blockIdx.z == 0) ? W0 : (blockIdx.z == 1) ? W1 :
                     (blockIdx.z == 2) ? W2 : W3;
    size_t wo = (size_t)blockIdx.z * CC * CC;
    __shared__ float t[32][33];
    int n0 = blockIdx.x * 32, k0 = blockIdx.y * 32;
    int tx = threadIdx.x, ty = threadIdx.y;
#pragma unroll
    for (int i = 0; i < 4; i++)
        t[ty + 8 * i][tx] = W[(size_t)(k0 + ty + 8 * i) * CC + n0 + tx];
    __syncthreads();
#pragma unroll
    for (int i = 0; i < 4; i++) {
        float a = t[tx][ty + 8 * i];
        __half h = __float2half_rn(a);
        __half l = __float2half_rn(a - __half2float(h));
        size_t o = wo + (size_t)(n0 + ty + 8 * i) * CC + k0 + tx;
        Wh[o] = h; Wl[o] = l;
    }
}

// ======================= activation fp16 split (x only) =======================
__global__ __launch_bounds__(256) void split_kernel(
    const float4* __restrict__ A, __half2* __restrict__ Ah,
    __half2* __restrict__ Al, int n4)
{
    int i = blockIdx.x * 256 + threadIdx.x;
    if (i < n4) {
        float4 a = A[i];
        __half h0 = __float2half_rn(a.x);
        __half h1 = __float2half_rn(a.y);
        __half h2 = __float2half_rn(a.z);
        __half h3 = __float2half_rn(a.w);
        __half l0 = __float2half_rn(a.x - __half2float(h0));
        __half l1 = __float2half_rn(a.y - __half2float(h1));
        __half l2 = __float2half_rn(a.z - __half2float(h2));
        __half l3 = __float2half_rn(a.w - __half2float(h3));
        Ah[2 * i]     = __half2{h0, h1};
        Ah[2 * i + 1] = __half2{h2, h3};
        Al[2 * i]     = __half2{l0, l1};
        Al[2 * i + 1] = __half2{l2, l3};
    }
}

// ======================= inv softplus precompute =======================
__global__ void invsp_kernel(const float* __restrict__ sp)
{
    int c = blockIdx.x * 256 + threadIdx.x;
    if (c < CC) {
        float s = sp[c];
        float v = (s > 20.f) ? s : log1pf(expf(s));
        g_invsc[c] = 1.0f / v;
    }
}

// ======================= focusing kernel (warp-per-row) =======================
__global__ __launch_bounds__(256) void focus_kernel(float* __restrict__ q, float* __restrict__ k)
{
    float* t = blockIdx.y ? k : q;
    const int w    = threadIdx.x >> 5;
    const int lane = threadIdx.x & 31;
    const size_t row = (size_t)blockIdx.x * 8 + w;
    float4* p = (float4*)(t + row * CC);

    float vv[24];
    float s2 = 0.f, s6 = 0.f;
#pragma unroll
    for (int i = 0; i < 6; i++) {
        float4 x  = p[lane + i * 32];
        const float4 iv = ((const float4*)g_invsc)[lane + i * 32];
        float v0 = (fmaxf(x.x, 0.f) + 1e-6f) * iv.x;
        float v1 = (fmaxf(x.y, 0.f) + 1e-6f) * iv.y;
        float v2 = (fmaxf(x.z, 0.f) + 1e-6f) * iv.z;
        float v3 = (fmaxf(x.w, 0.f) + 1e-6f) * iv.w;
        float a0 = v0 * v0, a1 = v1 * v1, a2 = v2 * v2, a3 = v3 * v3;
        s2 += a0 + a1 + a2 + a3;
        float c0 = a0 * v0, c1 = a1 * v1, c2 = a2 * v2, c3 = a3 * v3;
        s6 += c0 * c0 + c1 * c1 + c2 * c2 + c3 * c3;
        vv[i * 4 + 0] = c0; vv[i * 4 + 1] = c1;
        vv[i * 4 + 2] = c2; vv[i * 4 + 3] = c3;
    }

#pragma unroll
    for (int o = 16; o > 0; o >>= 1) {
        s2 += __shfl_xor_sync(0xffffffffu, s2, o);
        s6 += __shfl_xor_sync(0xffffffffu, s6, o);
    }
    float f = sqrtf(s2 / s6);

#pragma unroll
    for (int i = 0; i < 6; i++) {
        float4 o4;
        o4.x = vv[i * 4 + 0] * f;
        o4.y = vv[i * 4 + 1] * f;
        o4.z = vv[i * 4 + 2] * f;
        o4.w = vv[i * 4 + 3] * f;
        p[lane + i * 32] = o4;
    }
}

// ======================= kv = k^T v per (b,h), ksum fused, f32x2 ===========
__global__ __launch_bounds__(256) void kv_kernel(
    const float* __restrict__ k, const float* __restrict__ v,
    float* __restrict__ kv, float* __restrict__ ksum)
{
    int bh = blockIdx.x;
    int b = bh >> 3, h = bh & 7;
    __shared__ float ks[28][HD];
    __shared__ float vs[28][HD];
    const int tid = threadIdx.x;
    const int ty = tid >> 4;
    const int tx = tid & 15;

    uint64_t acc2[6][3];
    float cs[6];
#pragma unroll
    for (int i = 0; i < 6; i++) {
        cs[i] = 0.f;
#pragma unroll
        for (int l = 0; l < 3; l++) acc2[i][l] = 0ull;
    }

    const float* kb = k + (size_t)b * NN * CC + h * HD;
    const float* vb = v + (size_t)b * NN * CC + h * HD;

    for (int j0 = 0; j0 < NN; j0 += 28) {
        for (int idx = tid; idx < 28 * HD; idx += 256) {
            int j = idx / HD, c = idx % HD;
            ks[j][c] = kb[(size_t)(j0 + j) * CC + c];
            vs[j][c] = vb[(size_t)(j0 + j) * CC + c];
        }
        __syncthreads();
#pragma unroll 7
        for (int j = 0; j < 28; j++) {
            const float2* kp = (const float2*)(&ks[j][ty * 6]);
            float2 k01 = kp[0], k23 = kp[1], k45 = kp[2];
            uint64_t kd[6];
            kd[0] = d2(k01.x, k01.x); kd[1] = d2(k01.y, k01.y);
            kd[2] = d2(k23.x, k23.x); kd[3] = d2(k23.y, k23.y);
            kd[4] = d2(k45.x, k45.x); kd[5] = d2(k45.y, k45.y);
            const uint64_t* vp = (const uint64_t*)(&vs[j][tx * 6]);
            uint64_t v0 = vp[0], v1 = vp[1], v2 = vp[2];
            if (tx == 0) {
                cs[0] += k01.x; cs[1] += k01.y;
                cs[2] += k23.x; cs[3] += k23.y;
                cs[4] += k45.x; cs[5] += k45.y;
            }
#pragma unroll
            for (int i = 0; i < 6; i++) {
                FMA2(acc2[i][0], kd[i], v0);
                FMA2(acc2[i][1], kd[i], v1);
                FMA2(acc2[i][2], kd[i], v2);
            }
        }
        __syncthreads();
    }

#pragma unroll
    for (int i = 0; i < 6; i++)
#pragma unroll
        for (int l = 0; l < 3; l++) {
            float2 pr = u2(acc2[i][l]);
            *(float2*)(kv + (size_t)bh * HD * HD + (ty * 6 + i) * HD + tx * 6 + l * 2) = pr;
        }
    if (tx == 0) {
#pragma unroll
        for (int i = 0; i < 6; i++)
            ksum[bh * HD + ty * 6 + i] = cs[i];
    }
}

// ======================= attention-out + dwc -> fp16, channel-split, f32x2 ==
// q staged through smem in 4 chunks of 24 channels (coalesced, conflict-free).
#define HC 48
#define VST 50      // padded v row stride
#define QST 25      // padded q chunk row stride (coprime with 32)
#define A_KV   0                       // 96*48 = 4608
#define A_KSM  4608                    // 96
#define A_WS   4704                    // 25*48 = 1200 (tap-major)
#define A_BS   5904                    // 48
#define A_QB   5952                    // 196*25 = 4900
#define A_VS   10852                   // 196*50 = 9800
#define SMEM_AD ((A_VS + NN*VST) * 4)  // 82608 bytes

__global__ __launch_bounds__(224, 2) void attn_dwc_kernel(
    const float* __restrict__ q, const float* __restrict__ kv,
    const float* __restrict__ ksum, const float* __restrict__ v,
    const float* __restrict__ w, const float* __restrict__ db,
    __half* __restrict__ ah)
{
    extern __shared__ float sm[];
    int bh = blockIdx.x;
    int b = bh >> 3, h = bh & 7;
    int ch0 = blockIdx.y * HC;
    const int tid = threadIdx.x;

    for (int idx = tid; idx < HD * HC; idx += 224) {
        int c = idx / HC, d = idx % HC;
        sm[A_KV + idx] = kv[(size_t)bh * HD * HD + c * HD + ch0 + d];
    }
    for (int idx = tid; idx < NN * HC; idx += 224) {
        int p = idx / HC, c = idx % HC;
        sm[A_VS + p * VST + c] = v[((size_t)b * NN + p) * CC + h * HD + ch0 + c];
    }
    for (int idx = tid; idx < 25 * HC; idx += 224) {
        int tap = idx / HC, c = idx % HC;
        sm[A_WS + idx] = w[(ch0 + c) * 25 + tap];
    }
    if (tid < HD) sm[A_KSM + tid] = ksum[bh * HD + tid];
    if (tid < HC) sm[A_BS + tid] = db[ch0 + tid];

    uint64_t acc2[24];
#pragma unroll
    for (int d = 0; d < 24; d++) acc2[d] = 0ull;
    float zacc = 0.f;

    const float* qb = q + (size_t)b * NN * CC + h * HD;

    // 4 chunks of 24 q-channels, staged in smem (coalesced load)
    for (int ch = 0; ch < 4; ch++) {
        __syncthreads();   // prior consume done (and first iter: loads above done)
        for (int idx = tid; idx < NN * 24; idx += 224) {
            int rq = idx / 24, c = idx % 24;
            sm[A_QB + rq * QST + c] = qb[(size_t)rq * CC + ch * 24 + c];
        }
        __syncthreads();
        if (tid < NN) {
#pragma unroll
            for (int cc = 0; cc < 24; cc++) {
                int c = ch * 24 + cc;
                float qv = sm[A_QB + tid * QST + cc];
                zacc = fmaf(qv, sm[A_KSM + c], zacc);
                uint64_t qd = d2(qv, qv);
                const uint64_t* kr = (const uint64_t*)(sm + A_KV + c * HC);
#pragma unroll
                for (int d = 0; d < 24; d++) FMA2(acc2[d], qd, kr[d]);
            }
        }
    }

    if (tid < NN) {
        float zi = 1.f / (zacc + 1e-6f);
        // acc = acc*zi + bias
        {
            uint64_t zd = d2(zi, zi);
            const uint64_t* bs = (const uint64_t*)(sm + A_BS);
#pragma unroll
            for (int d = 0; d < 24; d++) FMA2S(acc2[d], zd, bs[d]);
        }
        // dwc taps accumulate into acc
        const int y = tid / 14, x = tid % 14;
#pragma unroll
        for (int dy = -2; dy <= 2; dy++) {
            int yy = y + dy;
            if ((unsigned)yy >= 14u) continue;
#pragma unroll
            for (int dx = -2; dx <= 2; dx++) {
                int xx = x + dx;
                if ((unsigned)xx >= 14u) continue;
                int tap = (dy + 2) * 5 + (dx + 2);
                const uint64_t* wr = (const uint64_t*)(sm + A_WS + tap * HC);
                const uint64_t* vr = (const uint64_t*)(sm + A_VS + (yy * 14 + xx) * VST);
#pragma unroll
                for (int d = 0; d < 24; d++) FMA2(acc2[d], wr[d], vr[d]);
            }
        }

        __half* orow = ah + ((size_t)b * NN + tid) * CC + h * HD + ch0;
#pragma unroll
        for (int d = 0; d < 24; d++) {
            float2 r = u2(acc2[d]);
            *(__half2*)(orow + d * 2) = __floats2half2_rn(r.x, r.y);
        }
    }
}

// ======================= launch =======================
extern "C" void kernel_launch(void* const* d_in, const int* in_sizes, int n_in,
                              void* d_out, int out_size)
{
    const float* x   = (const float*)d_in[0];
    const float* Wq  = (const float*)d_in[1];
    const float* bq  = (const float*)d_in[2];
    const float* Wk  = (const float*)d_in[3];
    const float* bk  = (const float*)d_in[4];
    const float* Wv  = (const float*)d_in[5];
    const float* bv  = (const float*)d_in[6];
    const float* pos = (const float*)d_in[7];
    const float* sp  = (const float*)d_in[8];
    const float* dw  = (const float*)d_in[9];
    const float* db  = (const float*)d_in[10];
    const float* Wp  = (const float*)d_in[11];
    const float* bp  = (const float*)d_in[12];
    float* out = (float*)d_out;

    float *Q, *K, *V, *KV, *KS;
    __half *xh, *xl, *ah, *wh, *wl;
    cudaGetSymbolAddress((void**)&Q,  g_Q);
    cudaGetSymbolAddress((void**)&K,  g_K);
    cudaGetSymbolAddress((void**)&V,  g_V);
    cudaGetSymbolAddress((void**)&KV, g_KV);
    cudaGetSymbolAddress((void**)&KS, g_KS);
    cudaGetSymbolAddress((void**)&xh, g_xh);
    cudaGetSymbolAddress((void**)&xl, g_xl);
    cudaGetSymbolAddress((void**)&ah, g_ah);
    cudaGetSymbolAddress((void**)&wh, g_wh);
    cudaGetSymbolAddress((void**)&wl, g_wl);

    cudaFuncSetAttribute(gemm3_f16, cudaFuncAttributeMaxDynamicSharedMemorySize, SMEM_G3);
    cudaFuncSetAttribute(gemm2_f16, cudaFuncAttributeMaxDynamicSharedMemorySize, 3 * STGB);
    cudaFuncSetAttribute(attn_dwc_kernel, cudaFuncAttributeMaxDynamicSharedMemorySize, SMEM_AD);

    const size_t WSZ = (size_t)CC * CC;
    const int n4 = MROWS * CC / 4;

    // 0: weight transpose + split, 1: x split, 2: softplus reciprocal
    wsplit_kernel<<<dim3(24, 24, 4), dim3(32, 8)>>>(Wq, Wk, Wv, Wp, wh, wl);
    split_kernel<<<(n4 + 255) / 256, 256>>>((const float4*)x,
        (__half2*)xh, (__half2*)xl, n4);
    invsp_kernel<<<3, 256>>>(sp);

    dim3 gg3(CC / 256, MROWS / 128);   // (3, 196)
    dim3 gg2(CC / 128, MROWS / 128);   // (6, 196)
    // 3: Q (3-term), 4: K (3-term) — profiler control window
    gemm3_f16<<<gg3, 256, SMEM_G3>>>(xh, xl, wh + 0 * WSZ, wl + 0 * WSZ, bq, pos, Q, 0);
    gemm3_f16<<<gg3, 256, SMEM_G3>>>(xh, xl, wh + 1 * WSZ, wl + 1 * WSZ, bk, pos, K, 1);
    // 5: V (2-term)
    gemm2_f16<<<gg2, 256, 3 * STGB>>>(xh, wh + 2 * WSZ, wl + 2 * WSZ, bv, pos, V, 0);

    // 6: focusing (warp-per-row)
    focus_kernel<<<dim3(MROWS / 8, 2), 256>>>(Q, K);

    // 7: kv + ksum (f32x2), 8: attn-out + dwc -> fp16 ah (q smem-staged)
    kv_kernel<<<BHD, 256>>>(K, V, KV, KS);
    attn_dwc_kernel<<<dim3(BHD, 2), 224, SMEM_AD>>>(Q, KV, KS, V, dw, db, ah);

    // 9: output projection (2-term, reads ah directly)
    gemm2_f16<<<gg2, 256, 3 * STGB>>>(ah, wh + 3 * WSZ, wl + 3 * WSZ, bp, pos, out, 0);
}